// round 12
// baseline (speedup 1.0000x reference)
#include <cuda_runtime.h>
#include <cuda_fp16.h>
#include <cstdint>

// ---------------- problem constants ----------------
constexpr int MODAL  = 8;
constexpr int DMODEL = 1024;
constexpr int NHEAD  = 16;
constexpr int DK     = 64;
constexpr int SEXT   = 64;
constexpr int BSZ    = 4096;
constexpr int ROWS   = BSZ * MODAL;   // 32768

// ---------------- scratch (device globals) ----------------
__device__ float g_x  [(size_t)ROWS * DMODEL];
__device__ float g_scores[(size_t)BSZ * NHEAD * MODAL * MODAL];
// fp16 operands
__device__ __half g_qh  [(size_t)ROWS * DMODEL];
__device__ __half g_kh  [(size_t)ROWS * DMODEL];
__device__ __half g_vh  [(size_t)ROWS * DMODEL];
__device__ __half g_qph [(size_t)ROWS * DMODEL];
__device__ __half g_kph [(size_t)ROWS * DMODEL];
__device__ __half g_vph [(size_t)ROWS * DMODEL];
__device__ __half g_atth[(size_t)ROWS * DMODEL];
__device__ __half g_xh  [(size_t)ROWS * DMODEL];
__device__ __half g_wqh [(size_t)DMODEL * DMODEL];
__device__ __half g_wkh [(size_t)DMODEL * DMODEL];
__device__ __half g_wvh [(size_t)DMODEL * DMODEL];
__device__ __half g_wfch[(size_t)DMODEL * DMODEL];
__device__ __half g_wmkh[(size_t)SEXT * DMODEL];
__device__ __half g_wmvh[(size_t)DMODEL * SEXT];
__device__ unsigned g_min_u;

// ---------------- global atomic-min encoding ----------------
__device__ __forceinline__ unsigned enc_min(float f) {
    unsigned u = __float_as_uint(f);
    return (u & 0x80000000u) ? ~u : (u | 0x80000000u);
}
__device__ __forceinline__ float dec_min(unsigned k) {
    return (k & 0x80000000u) ? __uint_as_float(k ^ 0x80000000u)
                             : __uint_as_float(~k);
}
__global__ void init_min_kernel() { g_min_u = 0xFFFFFFFFu; }

// ---------------- helpers ----------------
__device__ __forceinline__ void mma_f16(float* c, const unsigned* a, const unsigned* b) {
    asm volatile(
        "mma.sync.aligned.m16n8k16.row.col.f32.f16.f16.f32 "
        "{%0,%1,%2,%3}, {%4,%5,%6,%7}, {%8,%9}, {%0,%1,%2,%3};\n"
        : "+f"(c[0]), "+f"(c[1]), "+f"(c[2]), "+f"(c[3])
        : "r"(a[0]), "r"(a[1]), "r"(a[2]), "r"(a[3]),
          "r"(b[0]), "r"(b[1]));
}
__device__ __forceinline__ void ldsm4(unsigned& r0, unsigned& r1, unsigned& r2, unsigned& r3,
                                      uint32_t a) {
    asm volatile("ldmatrix.sync.aligned.m8n8.x4.shared.b16 {%0,%1,%2,%3}, [%4];"
                 : "=r"(r0), "=r"(r1), "=r"(r2), "=r"(r3) : "r"(a));
}
__device__ __forceinline__ uint32_t smem_u32(const void* p) {
    uint32_t a;
    asm("{ .reg .u64 t; cvta.to.shared.u64 t, %1; cvt.u32.u64 %0, t; }" : "=r"(a) : "l"(p));
    return a;
}
__device__ __forceinline__ void cp16(uint32_t dst, const void* src) {
    asm volatile("cp.async.cg.shared.global [%0], [%1], 16;" :: "r"(dst), "l"(src));
}
#define CP_COMMIT() asm volatile("cp.async.commit_group;" ::: "memory")
#define CP_WAIT0()  asm volatile("cp.async.wait_group 0;" ::: "memory")
#define CP_WAIT1()  asm volatile("cp.async.wait_group 1;" ::: "memory")
#define CP_WAIT2()  asm volatile("cp.async.wait_group 2;" ::: "memory")

// unpack 8 halves (one uint4) -> 8 floats at dst
__device__ __forceinline__ void h8_to_f8(uint4 u, float* dst) {
    const __half2* hp = (const __half2*)&u;
    float2 f0 = __half22float2(hp[0]);
    float2 f1 = __half22float2(hp[1]);
    float2 f2 = __half22float2(hp[2]);
    float2 f3 = __half22float2(hp[3]);
    *(float4*)dst       = make_float4(f0.x, f0.y, f1.x, f1.y);
    *(float4*)(dst + 4) = make_float4(f2.x, f2.y, f3.x, f3.y);
}

// ---------------- fused fp32->fp16 conversions ----------------
__global__ void __launch_bounds__(256) cvt_act_kernel(
    const float4* __restrict__ s0, const float4* __restrict__ s1, const float4* __restrict__ s2,
    __half2* __restrict__ d0, __half2* __restrict__ d1, __half2* __restrict__ d2, int n4)
{
    const int z = blockIdx.y;
    const float4* s = (z == 0) ? s0 : (z == 1) ? s1 : s2;
    __half2* d = (z == 0) ? d0 : (z == 1) ? d1 : d2;
    int i = blockIdx.x * 256 + threadIdx.x;
    if (i < n4) {
        float4 v = s[i];
        d[2 * i]     = __float22half2_rn(make_float2(v.x, v.y));
        d[2 * i + 1] = __float22half2_rn(make_float2(v.z, v.w));
    }
}

__global__ void __launch_bounds__(256) cvt_w_kernel(
    const float4* __restrict__ s0, const float4* __restrict__ s1,
    const float4* __restrict__ s2, const float4* __restrict__ s3,
    const float4* __restrict__ s4, const float4* __restrict__ s5,
    __half2* __restrict__ d0, __half2* __restrict__ d1,
    __half2* __restrict__ d2, __half2* __restrict__ d3,
    __half2* __restrict__ d4, __half2* __restrict__ d5,
    int nbig, int nsmall)
{
    const int z = blockIdx.y;
    const float4* sa[6] = { s0, s1, s2, s3, s4, s5 };
    __half2* da[6] = { d0, d1, d2, d3, d4, d5 };
    const int n4 = (z < 4) ? nbig : nsmall;
    int i = blockIdx.x * 256 + threadIdx.x;
    if (i < n4) {
        float4 v = sa[z][i];
        da[z][2 * i]     = __float22half2_rn(make_float2(v.x, v.y));
        da[z][2 * i + 1] = __float22half2_rn(make_float2(v.z, v.w));
    }
}

// =====================================================================
// Shared GEMM body: C[M,N] = A[M,K] * B[N,K]^T (+ Res fp32).
// BM=128, BK=64, BN in {128,64}. 256 thr, 8 warps (4Mx2N), 3-stage cp.async.
// =====================================================================
template<int BN, bool RES, bool OUTH>
__device__ __forceinline__ void gemm_body(
    const __half* __restrict__ A, const __half* __restrict__ B,
    const float* __restrict__ Res, void* __restrict__ Cv, int K, int N,
    char* smc, int bm, int bn)
{
    constexpr int ABYTES = 128 * 128;
    constexpr int BBYTES = BN * 128;
    constexpr int STB    = ABYTES + BBYTES;
    constexpr int BCH    = BN * 8 / 256;
    constexpr int WNT    = BN / 2;
    constexpr int NT     = WNT / 8;
    constexpr int MT     = 2;

    const uint32_t sbase = smem_u32(smc);
    const int tid  = threadIdx.x;
    const int lane = tid & 31;
    const int wid  = tid >> 5;
    const int wm   = wid & 3;
    const int wn   = wid >> 2;

    const int mA = tid >> 3;
    const int cA = tid & 7;
    const int nk = K / 64;

    auto issue = [&](int kt, int s) {
        const uint32_t so = (uint32_t)s * STB;
        const int k0 = kt * 64;
#pragma unroll
        for (int i = 0; i < 4; i++) {
            const int m = mA + 32 * i;
            const uint32_t dst = sbase + so + (uint32_t)m * 128u + (uint32_t)((cA ^ (m & 7)) << 4);
            cp16(dst, A + (size_t)(bm + m) * K + k0 + cA * 8);
        }
#pragma unroll
        for (int i = 0; i < BCH; i++) {
            const int m = mA + 32 * i;
            const uint32_t dst = sbase + so + (uint32_t)ABYTES
                               + (uint32_t)m * 128u + (uint32_t)((cA ^ (m & 7)) << 4);
            cp16(dst, B + (size_t)(bn + m) * K + k0 + cA * 8);
        }
    };

    float acc[MT][NT][4];
#pragma unroll
    for (int i = 0; i < MT; i++)
#pragma unroll
        for (int j = 0; j < NT; j++)
#pragma unroll
            for (int t = 0; t < 4; t++) acc[i][j][t] = 0.f;

    issue(0, 0); CP_COMMIT();
    if (nk > 1) issue(1, 1);
    CP_COMMIT();

    uint32_t aaddr[MT];
    {
        const int g = lane >> 3;
        const int arow_in = (g & 1) * 8 + (lane & 7);
        const uint32_t apar = (uint32_t)(g >> 1);
#pragma unroll
        for (int i = 0; i < MT; i++) {
            const int row = wm * 32 + i * 16 + arow_in;
            aaddr[i] = (uint32_t)row * 128u + ((((uint32_t)row & 7u) ^ apar) << 4);
        }
    }
    uint32_t baddr[NT / 2];
    {
        const int g = lane >> 3;
        const int nrow_in = ((g >> 1) & 1) * 8 + (lane & 7);
        const uint32_t bpar = (uint32_t)(g & 1);
#pragma unroll
        for (int jp = 0; jp < NT / 2; jp++) {
            const int n = wn * WNT + jp * 16 + nrow_in;
            baddr[jp] = (uint32_t)n * 128u + ((((uint32_t)n & 7u) ^ bpar) << 4);
        }
    }

    for (int kt = 0; kt < nk; kt++) {
        const int s = kt % 3;
        if (kt + 2 < nk) issue(kt + 2, (kt + 2) % 3);
        CP_COMMIT();
        CP_WAIT2();
        __syncthreads();

        const uint32_t sa = sbase + (uint32_t)s * STB;
        const uint32_t sb = sa + ABYTES;

#pragma unroll
        for (int ks = 0; ks < 4; ks++) {
            const uint32_t kx = (uint32_t)(2 * ks) << 4;
            unsigned af[MT][4], bf[NT][2];
#pragma unroll
            for (int i = 0; i < MT; i++)
                ldsm4(af[i][0], af[i][1], af[i][2], af[i][3], sa + (aaddr[i] ^ kx));
#pragma unroll
            for (int jp = 0; jp < NT / 2; jp++)
                ldsm4(bf[2 * jp][0], bf[2 * jp][1], bf[2 * jp + 1][0], bf[2 * jp + 1][1],
                      sb + (baddr[jp] ^ kx));
#pragma unroll
            for (int i = 0; i < MT; i++)
#pragma unroll
                for (int j = 0; j < NT; j++)
                    mma_f16(acc[i][j], af[i], bf[j]);
        }
        __syncthreads();
    }

#pragma unroll
    for (int i = 0; i < MT; i++) {
#pragma unroll
        for (int j = 0; j < NT; j++) {
            const int r0 = bm + wm * 32 + i * 16 + (lane >> 2);
            const int c0 = bn + wn * WNT + j * 8 + (lane & 3) * 2;
            float2 v0 = make_float2(acc[i][j][0], acc[i][j][1]);
            float2 v1 = make_float2(acc[i][j][2], acc[i][j][3]);
            if (OUTH) {
                __half* Co = (__half*)Cv;
                *(__half2*)&Co[(size_t)r0 * N + c0]       = __floats2half2_rn(v0.x, v0.y);
                *(__half2*)&Co[(size_t)(r0 + 8) * N + c0] = __floats2half2_rn(v1.x, v1.y);
            } else {
                float* Cf = (float*)Cv;
                if (RES) {
                    float2 ra = *(const float2*)&Res[(size_t)r0 * N + c0];
                    float2 rb = *(const float2*)&Res[(size_t)(r0 + 8) * N + c0];
                    v0.x += ra.x; v0.y += ra.y;
                    v1.x += rb.x; v1.y += rb.y;
                }
                *(float2*)&Cf[(size_t)r0 * N + c0] = v0;
                *(float2*)&Cf[(size_t)(r0 + 8) * N + c0] = v1;
            }
        }
    }
}

// ---- fused 3-way projection GEMM (grid.z selects q/k/v) ----
__global__ void __launch_bounds__(256, 2) gemm_proj3(
    const __half* A0, const __half* A1, const __half* A2,
    const __half* B0, const __half* B1, const __half* B2,
    __half* C0, __half* C1, __half* C2)
{
    extern __shared__ char smc[];
    const int z = blockIdx.z;
    const __half* A = (z == 0) ? A0 : (z == 1) ? A1 : A2;
    const __half* B = (z == 0) ? B0 : (z == 1) ? B1 : B2;
    __half* C = (z == 0) ? C0 : (z == 1) ? C1 : C2;
    gemm_body<128, false, true>(A, B, nullptr, C, DMODEL, DMODEL,
                                smc, blockIdx.y * 128, blockIdx.x * 128);
}

// ---- FC GEMM: x = attn_out @ Wfc^T + q (fp32 out) ----
__global__ void __launch_bounds__(256, 2) gemm_fc(
    const __half* __restrict__ A, const __half* __restrict__ B,
    const float* __restrict__ Res, float* __restrict__ C)
{
    extern __shared__ char smc[];
    gemm_body<128, true, false>(A, B, Res, C, DMODEL, DMODEL,
                                smc, blockIdx.y * 128, blockIdx.x * 128);
}

// =====================================================================
// Fully fused external attention:
//   phase 1: xa = g_xh @ Wmk^T (128x64 tile, K=1024, 2-stage pipeline)
//   epilogue: softmax over modal (8-row groups), renorm over S,
//             a -> fp16 swizzled smem (rsum folded)
//   phase 2: out += a @ Wmv^T  (8 N-tiles of 128, K=64, 2-buf B ring)
// smem: AA[0,16K) BB[16K,48K) stages[48K,96K) (tile overlays stages)
// =====================================================================
__global__ void __launch_bounds__(256, 2) gemm_xa_full(
    const __half* __restrict__ Xh, const __half* __restrict__ Wmk,
    const __half* __restrict__ Wmv, float* __restrict__ out)
{
    constexpr int AABYTES = 16384;
    constexpr int BBOFF   = 16384;
    constexpr int STOFF   = 49152;           // phase-1 stages base
    constexpr int STB     = 128 * 128 + 64 * 128;  // 24576 per stage
    constexpr int TP      = 66;

    extern __shared__ char smc[];
    const uint32_t sbase = smem_u32(smc);

    const int tid  = threadIdx.x;
    const int lane = tid & 31;
    const int wid  = tid >> 5;
    const int wm   = wid & 3;
    const int wn   = wid >> 2;
    const int bm   = blockIdx.y * 128;

    const int mA = tid >> 3;
    const int cA = tid & 7;
    constexpr int nk = DMODEL / 64;   // 16

    // ---- phase 1 cp.async (A=Xh 128 rows, B=Wmk 64 rows) ----
    auto issue1 = [&](int kt, int s) {
        const uint32_t so = STOFF + (uint32_t)s * STB;
        const int k0 = kt * 64;
#pragma unroll
        for (int i = 0; i < 4; i++) {
            const int m = mA + 32 * i;
            const uint32_t dst = sbase + so + (uint32_t)m * 128u + (uint32_t)((cA ^ (m & 7)) << 4);
            cp16(dst, Xh + (size_t)(bm + m) * DMODEL + k0 + cA * 8);
        }
#pragma unroll
        for (int i = 0; i < 2; i++) {
            const int m = mA + 32 * i;
            const uint32_t dst = sbase + so + 16384u
                               + (uint32_t)m * 128u + (uint32_t)((cA ^ (m & 7)) << 4);
            cp16(dst, Wmk + (size_t)m * DMODEL + k0 + cA * 8);
        }
    };

    float acc[2][4][4];
#pragma unroll
    for (int i = 0; i < 2; i++)
#pragma unroll
        for (int j = 0; j < 4; j++)
#pragma unroll
            for (int t = 0; t < 4; t++) acc[i][j][t] = 0.f;

    issue1(0, 0); CP_COMMIT();
    issue1(1, 1); CP_COMMIT();

    // fragment bases
    uint32_t aaddr[2];
    {
        const int g = lane >> 3;
        const int arow_in = (g & 1) * 8 + (lane & 7);
        const uint32_t apar = (uint32_t)(g >> 1);
#pragma unroll
        for (int i = 0; i < 2; i++) {
            const int row = wm * 32 + i * 16 + arow_in;
            aaddr[i] = (uint32_t)row * 128u + ((((uint32_t)row & 7u) ^ apar) << 4);
        }
    }
    const int gB = lane >> 3;
    const int nrow_in = ((gB >> 1) & 1) * 8 + (lane & 7);
    const uint32_t bpar = (uint32_t)(gB & 1);
    uint32_t baddr64[2];   // phase 1 (BN=64, WNT=32)
#pragma unroll
    for (int jp = 0; jp < 2; jp++) {
        const int n = wn * 32 + jp * 16 + nrow_in;
        baddr64[jp] = (uint32_t)n * 128u + ((((uint32_t)n & 7u) ^ bpar) << 4);
    }
    uint32_t baddr128[4];  // phase 2 (BN=128, WNT=64)
#pragma unroll
    for (int jp = 0; jp < 4; jp++) {
        const int n = wn * 64 + jp * 16 + nrow_in;
        baddr128[jp] = (uint32_t)n * 128u + ((((uint32_t)n & 7u) ^ bpar) << 4);
    }

    // ---- phase 1 mainloop (2-stage) ----
    for (int kt = 0; kt < nk; kt++) {
        if (kt + 1 < nk) { CP_WAIT1(); } else { CP_WAIT0(); }
        __syncthreads();
        const uint32_t sa = sbase + STOFF + (uint32_t)(kt & 1) * STB;
        const uint32_t sb = sa + 16384u;
#pragma unroll
        for (int ks = 0; ks < 4; ks++) {
            const uint32_t kx = (uint32_t)(2 * ks) << 4;
            unsigned af[2][4], bf[4][2];
#pragma unroll
            for (int i = 0; i < 2; i++)
                ldsm4(af[i][0], af[i][1], af[i][2], af[i][3], sa + (aaddr[i] ^ kx));
#pragma unroll
            for (int jp = 0; jp < 2; jp++)
                ldsm4(bf[2 * jp][0], bf[2 * jp][1], bf[2 * jp + 1][0], bf[2 * jp + 1][1],
                      sb + (baddr64[jp] ^ kx));
#pragma unroll
            for (int i = 0; i < 2; i++)
#pragma unroll
                for (int j = 0; j < 4; j++)
                    mma_f16(acc[i][j], af[i], bf[j]);
        }
        __syncthreads();
        if (kt + 2 < nk) { issue1(kt + 2, kt & 1); CP_COMMIT(); }
    }

    // ---- phase 2 B-loads (Wmv tiles 0,1) issued early ----
    auto issueB2 = [&](int nt, int buf) {
#pragma unroll
        for (int i = 0; i < 4; i++) {
            const int m = mA + 32 * i;
            const uint32_t dst = sbase + BBOFF + (uint32_t)buf * 16384u
                               + (uint32_t)m * 128u + (uint32_t)((cA ^ (m & 7)) << 4);
            cp16(dst, Wmv + (size_t)(nt * 128 + m) * SEXT + cA * 8);
        }
    };
    issueB2(0, 0); CP_COMMIT();
    issueB2(1, 1); CP_COMMIT();

    // ---- ext-attention epilogue in smem ----
    float* tile = (float*)(smc + STOFF);        // [128][TP]
    float* rsum = tile + 128 * TP;              // [128]
#pragma unroll
    for (int i = 0; i < 2; i++) {
#pragma unroll
        for (int j = 0; j < 4; j++) {
            const int rl = wm * 32 + i * 16 + (lane >> 2);
            const int cl = wn * 32 + j * 8 + (lane & 3) * 2;
            *(float2*)&tile[rl * TP + cl]       = make_float2(acc[i][j][0], acc[i][j][1]);
            *(float2*)&tile[(rl + 8) * TP + cl] = make_float2(acc[i][j][2], acc[i][j][3]);
        }
    }
    __syncthreads();

    for (int p = tid; p < 16 * SEXT; p += 256) {
        const int bl = p >> 6, s = p & 63;
        float* col = &tile[(bl * 8) * TP + s];
        float mx = col[0];
#pragma unroll
        for (int m = 1; m < MODAL; m++) mx = fmaxf(mx, col[m * TP]);
        float sum = 0.f;
        float e[MODAL];
#pragma unroll
        for (int m = 0; m < MODAL; m++) { e[m] = expf(col[m * TP] - mx); sum += e[m]; }
        const float is = 1.f / sum;
#pragma unroll
        for (int m = 0; m < MODAL; m++) col[m * TP] = e[m] * is;
    }
    __syncthreads();

    for (int r = tid; r < 128; r += 256) {
        float t = 0.f;
        const float* row = &tile[r * TP];
#pragma unroll
        for (int s = 0; s < SEXT; s++) t += row[s];
        rsum[r] = 1.f / t;
    }
    __syncthreads();

    // a -> fp16 swizzled AA (rsum folded): 1024 16B chunks
    for (int idx = tid; idx < 1024; idx += 256) {
        const int r = idx >> 3, c = idx & 7;
        const float rs = rsum[r];
        const float* src = &tile[r * TP + c * 8];
        uint4 pack;
        __half2* hp = (__half2*)&pack;
        hp[0] = __floats2half2_rn(src[0] * rs, src[1] * rs);
        hp[1] = __floats2half2_rn(src[2] * rs, src[3] * rs);
        hp[2] = __floats2half2_rn(src[4] * rs, src[5] * rs);
        hp[3] = __floats2half2_rn(src[6] * rs, src[7] * rs);
        *(uint4*)(smc + (uint32_t)r * 128u + (uint32_t)((c ^ (r & 7)) << 4)) = pack;
    }
    __syncthreads();

    // ---- phase 2: out += a @ Wmv^T, 8 N-tiles ----
    for (int nt = 0; nt < 8; nt++) {
        if (nt + 1 < 8) { CP_WAIT1(); } else { CP_WAIT0(); }
        __syncthreads();
        const uint32_t sb = sbase + BBOFF + (uint32_t)(nt & 1) * 16384u;

        float acc2[2][8][4];
#pragma unroll
        for (int i = 0; i < 2; i++)
#pragma unroll
            for (int j = 0; j < 8; j++)
#pragma unroll
                for (int t = 0; t < 4; t++) acc2[i][j][t] = 0.f;

#pragma unroll
        for (int ks = 0; ks < 4; ks++) {
            const uint32_t kx = (uint32_t)(2 * ks) << 4;
            unsigned af[2][4], bf[8][2];
#pragma unroll
            for (int i = 0; i < 2; i++)
                ldsm4(af[i][0], af[i][1], af[i][2], af[i][3], sbase + (aaddr[i] ^ kx));
#pragma unroll
            for (int jp = 0; jp < 4; jp++)
                ldsm4(bf[2 * jp][0], bf[2 * jp][1], bf[2 * jp + 1][0], bf[2 * jp + 1][1],
                      sb + (baddr128[jp] ^ kx));
#pragma unroll
            for (int i = 0; i < 2; i++)
#pragma unroll
                for (int j = 0; j < 8; j++)
                    mma_f16(acc2[i][j], af[i], bf[j]);
        }

        // epilogue: out = x + tile (residual already in out)
#pragma unroll
        for (int i = 0; i < 2; i++) {
#pragma unroll
            for (int j = 0; j < 8; j++) {
                const int r0 = bm + wm * 32 + i * 16 + (lane >> 2);
                const int c0 = nt * 128 + wn * 64 + j * 8 + (lane & 3) * 2;
                float2 ra = *(const float2*)&out[(size_t)r0 * DMODEL + c0];
                float2 rb = *(const float2*)&out[(size_t)(r0 + 8) * DMODEL + c0];
                ra.x += acc2[i][j][0]; ra.y += acc2[i][j][1];
                rb.x += acc2[i][j][2]; rb.y += acc2[i][j][3];
                *(float2*)&out[(size_t)r0 * DMODEL + c0] = ra;
                *(float2*)&out[(size_t)(r0 + 8) * DMODEL + c0] = rb;
            }
        }
        __syncthreads();
        if (nt + 2 < 8) { issueB2(nt + 2, nt & 1); CP_COMMIT(); }
    }
}

// ---------------- attention pass A: scores + global min (fp16 inputs) ----------------
constexpr int QPAD = DMODEL + 4;

extern __shared__ float dynsmem[];

__global__ void __launch_bounds__(256) attn_scores_kernel() {
    float* qs = dynsmem;
    float* ks = dynsmem + MODAL * QPAD;
    const int b = blockIdx.x, tid = threadIdx.x;
    const uint4* qg = (const uint4*)(g_qph + (size_t)b * MODAL * DMODEL);
    const uint4* kg = (const uint4*)(g_kph + (size_t)b * MODAL * DMODEL);
    for (int i = tid; i < MODAL * DMODEL / 8; i += 256) {
        int m = i >> 7, c = i & 127;
        h8_to_f8(qg[i], &qs[m * QPAD + c * 8]);
        h8_to_f8(kg[i], &ks[m * QPAD + c * 8]);
    }
    __syncthreads();

    float lmin = 3.4e38f;
    for (int s = tid; s < NHEAD * MODAL * MODAL; s += 256) {
        int h = s >> 6, m = (s >> 3) & 7, n = s & 7;
        const float4* qr = (const float4*)&qs[m * QPAD + h * DK];
        const float4* kr = (const float4*)&ks[n * QPAD + h * DK];
        float acc = 0.f;
#pragma unroll
        for (int d = 0; d < 16; d++) {
            float4 a = qr[d], c = kr[d];
            acc += a.x * c.x + a.y * c.y + a.z * c.z + a.w * c.w;
        }
        acc *= 0.125f;
        g_scores[(size_t)b * 1024 + s] = acc;
        lmin = fminf(lmin, acc);
    }
#pragma unroll
    for (int o = 16; o; o >>= 1) lmin = fminf(lmin, __shfl_xor_sync(0xffffffffu, lmin, o));
    __shared__ float wmn[8];
    if ((tid & 31) == 0) wmn[tid >> 5] = lmin;
    __syncthreads();
    if (tid == 0) {
        float m = wmn[0];
#pragma unroll
        for (int i = 1; i < 8; i++) m = fminf(m, wmn[i]);
        atomicMin(&g_min_u, enc_min(m));
    }
}

// ---------------- attention pass B (fp16 v input, fp16 output) ----------------
__global__ void __launch_bounds__(256) attn_out_kernel() {
    __shared__ float vs[MODAL * QPAD];
    __shared__ float sc[NHEAD * 64];
    __shared__ float aw[NHEAD * 64];
    const int b = blockIdx.x, tid = threadIdx.x;
    const float inv = 1.f / fabsf(dec_min(g_min_u));

    const uint4* vg = (const uint4*)(g_vph + (size_t)b * MODAL * DMODEL);
    for (int i = tid; i < MODAL * DMODEL / 8; i += 256) {
        int m = i >> 7, c = i & 127;
        h8_to_f8(vg[i], &vs[m * QPAD + c * 8]);
    }
    for (int i = tid; i < 1024; i += 256)
        sc[i] = g_scores[(size_t)b * 1024 + i] * inv;
    __syncthreads();

    if (tid < 128) {
        int h = tid >> 3, m = tid & 7;
        float r[8]; float ss = 0.f;
#pragma unroll
        for (int n = 0; n < 8; n++) { r[n] = sc[h * 64 + m * 8 + n]; ss += r[n] * r[n]; }
        float nrm = fmaxf(sqrtf(ss), 1e-12f);
        float rn = 1.f / nrm;
        float mx = -3.4e38f;
#pragma unroll
        for (int n = 0; n < 8; n++) { r[n] *= rn; mx = fmaxf(mx, r[n]); }
        float sum = 0.f;
#pragma unroll
        for (int n = 0; n < 8; n++) { r[n] = expf(r[n] - mx); sum += r[n]; }
        float is = 1.f / sum;
#pragma unroll
        for (int n = 0; n < 8; n++) aw[h * 64 + m * 8 + n] = r[n] * is;
    }
    __syncthreads();

    __half* og = g_atth + (size_t)b * MODAL * DMODEL;
    for (int o = tid; o < MODAL * DMODEL; o += 256) {
        int m = o >> 10, col = o & 1023, h = col >> 6;
        float acc = 0.f;
#pragma unroll
        for (int n = 0; n < 8; n++) acc += aw[h * 64 + m * 8 + n] * vs[n * QPAD + col];
        og[o] = __float2half_rn(acc);
    }
}

// ---------------- LayerNorm: fp32 x in -> fp32 out + fp16 copy ----------------
__global__ void __launch_bounds__(256) ln_kernel(
    const float* __restrict__ gamma, const float* __restrict__ beta,
    float* __restrict__ out)
{
    const int wid = threadIdx.x >> 5, lane = threadIdx.x & 31;
    const size_t row = (size_t)blockIdx.x * 8 + wid;
    const float4* xr = (const float4*)(g_x + row * DMODEL);
    float4 v[8];
    float s = 0.f, s2 = 0.f;
#pragma unroll
    for (int i = 0; i < 8; i++) {
        v[i] = xr[lane + 32 * i];
        s += v[i].x + v[i].y + v[i].z + v[i].w;
        s2 += v[i].x * v[i].x + v[i].y * v[i].y + v[i].z * v[i].z + v[i].w * v[i].w;
    }
#pragma unroll
    for (int o = 16; o; o >>= 1) {
        s += __shfl_xor_sync(0xffffffffu, s, o);
        s2 += __shfl_xor_sync(0xffffffffu, s2, o);
    }
    const float mu = s * (1.f / DMODEL);
    const float var = fmaxf(s2 * (1.f / DMODEL) - mu * mu, 0.f);
    const float rs = rsqrtf(var + 1e-10f);
    float4* orow = (float4*)(out + row * DMODEL);
    __half2* hrow = (__half2*)(g_xh + row * DMODEL);
    const float4* gm = (const float4*)gamma;
    const float4* bt = (const float4*)beta;
#pragma unroll
    for (int i = 0; i < 8; i++) {
        int c4 = lane + 32 * i;
        float4 g = gm[c4], bb = bt[c4], x = v[i], r;
        r.x = (x.x - mu) * rs * g.x + bb.x;
        r.y = (x.y - mu) * rs * g.y + bb.y;
        r.z = (x.z - mu) * rs * g.z + bb.z;
        r.w = (x.w - mu) * rs * g.w + bb.w;
        orow[c4] = r;
        hrow[2 * c4]     = __float22half2_rn(make_float2(r.x, r.y));
        hrow[2 * c4 + 1] = __float22half2_rn(make_float2(r.z, r.w));
    }
}

// ---------------- launch ----------------
extern "C" void kernel_launch(void* const* d_in, const int* in_sizes, int n_in,
                              void* d_out, int out_size)
{
    const float* q     = (const float*)d_in[0];
    const float* k     = (const float*)d_in[1];
    const float* v     = (const float*)d_in[2];
    const float* Wq    = (const float*)d_in[3];
    const float* Wk    = (const float*)d_in[4];
    const float* Wv    = (const float*)d_in[5];
    const float* Wfc   = (const float*)d_in[6];
    const float* gamma = (const float*)d_in[7];
    const float* beta  = (const float*)d_in[8];
    const float* Wmk   = (const float*)d_in[9];
    const float* Wmv   = (const float*)d_in[10];
    float* out = (float*)d_out;

    float *px;
    __half *pqh, *pkh, *pvh, *pqph, *pkph, *pvph, *patth, *pxh;
    __half *pwqh, *pwkh, *pwvh, *pwfch, *pwmkh, *pwmvh;
    cudaGetSymbolAddress((void**)&px,    g_x);
    cudaGetSymbolAddress((void**)&pqh,   g_qh);
    cudaGetSymbolAddress((void**)&pkh,   g_kh);
    cudaGetSymbolAddress((void**)&pvh,   g_vh);
    cudaGetSymbolAddress((void**)&pqph,  g_qph);
    cudaGetSymbolAddress((void**)&pkph,  g_kph);
    cudaGetSymbolAddress((void**)&pvph,  g_vph);
    cudaGetSymbolAddress((void**)&patth, g_atth);
    cudaGetSymbolAddress((void**)&pxh,   g_xh);
    cudaGetSymbolAddress((void**)&pwqh,  g_wqh);
    cudaGetSymbolAddress((void**)&pwkh,  g_wkh);
    cudaGetSymbolAddress((void**)&pwvh,  g_wvh);
    cudaGetSymbolAddress((void**)&pwfch, g_wfch);
    cudaGetSymbolAddress((void**)&pwmkh, g_wmkh);
    cudaGetSymbolAddress((void**)&pwmvh, g_wmvh);

    const int smem_sc = 2 * MODAL * QPAD * (int)sizeof(float);
    cudaFuncSetAttribute(attn_scores_kernel,
                         cudaFuncAttributeMaxDynamicSharedMemorySize, smem_sc);

    const int smem128 = 3 * (128 * 128 + 128 * 128);  // 98304 B
    const int smemXA  = 98304;
    cudaFuncSetAttribute(gemm_proj3,
                         cudaFuncAttributeMaxDynamicSharedMemorySize, smem128);
    cudaFuncSetAttribute(gemm_fc,
                         cudaFuncAttributeMaxDynamicSharedMemorySize, smem128);
    cudaFuncSetAttribute(gemm_xa_full,
                         cudaFuncAttributeMaxDynamicSharedMemorySize, smemXA);

    init_min_kernel<<<1, 1>>>();

    const int a4 = ROWS * DMODEL / 4;
    const int w4 = DMODEL * DMODEL / 4;
    const int s4 = SEXT * DMODEL / 4;

    // fused conversions: activations (3 slots), weights (6 slots)
    cvt_act_kernel<<<dim3((a4 + 255) / 256, 3), 256>>>(
        (const float4*)q, (const float4*)k, (const float4*)v,
        (__half2*)pqh, (__half2*)pkh, (__half2*)pvh, a4);
    cvt_w_kernel<<<dim3((w4 + 255) / 256, 6), 256>>>(
        (const float4*)Wq, (const float4*)Wk, (const float4*)Wv, (const float4*)Wfc,
        (const float4*)Wmk, (const float4*)Wmv,
        (__half2*)pwqh, (__half2*)pwkh, (__half2*)pwvh, (__half2*)pwfch,
        (__half2*)pwmkh, (__half2*)pwmvh, w4, s4);

    // fused q/k/v projections
    gemm_proj3<<<dim3(DMODEL / 128, ROWS / 128, 3), 256, smem128>>>(
        pqh, pkh, pvh, pwqh, pwkh, pwvh, pqph, pkph, pvph);

    attn_scores_kernel<<<BSZ, 256, smem_sc>>>();
    attn_out_kernel<<<BSZ, 256>>>();

    // x = attn_out @ Wfc^T + q (fp32 residual)
    gemm_fc<<<dim3(DMODEL / 128, ROWS / 128), 256, smem128>>>(patth, pwfch, q, px);

    // LayerNorm -> out (fp32) + g_xh (fp16)
    ln_kernel<<<ROWS / 8, 256>>>(gamma, beta, out);

    // fused: xa GEMM + ext-norm + final GEMM (out += a @ Wmv^T)
    gemm_xa_full<<<dim3(1, ROWS / 128), 256, smemXA>>>(pxh, pwmkh, pwmvh, out);
}

// round 13
// speedup vs baseline: 1.1348x; 1.1348x over previous
#include <cuda_runtime.h>
#include <cuda_fp16.h>
#include <cstdint>

// ---------------- problem constants ----------------
constexpr int MODAL  = 8;
constexpr int DMODEL = 1024;
constexpr int NHEAD  = 16;
constexpr int DK     = 64;
constexpr int SEXT   = 64;
constexpr int BSZ    = 4096;
constexpr int ROWS   = BSZ * MODAL;   // 32768

// ---------------- scratch (device globals) ----------------
__device__ float g_x  [(size_t)ROWS * DMODEL];
__device__ float g_scores[(size_t)BSZ * NHEAD * MODAL * MODAL];
// fp16 operands
__device__ __half g_qh  [(size_t)ROWS * DMODEL];
__device__ __half g_kh  [(size_t)ROWS * DMODEL];
__device__ __half g_vh  [(size_t)ROWS * DMODEL];
__device__ __half g_qph [(size_t)ROWS * DMODEL];
__device__ __half g_kph [(size_t)ROWS * DMODEL];
__device__ __half g_vph [(size_t)ROWS * DMODEL];
__device__ __half g_atth[(size_t)ROWS * DMODEL];
__device__ __half g_xh  [(size_t)ROWS * DMODEL];
__device__ __half g_ah  [(size_t)ROWS * SEXT];
__device__ __half g_wqh [(size_t)DMODEL * DMODEL];
__device__ __half g_wkh [(size_t)DMODEL * DMODEL];
__device__ __half g_wvh [(size_t)DMODEL * DMODEL];
__device__ __half g_wfch[(size_t)DMODEL * DMODEL];
__device__ __half g_wmkh[(size_t)SEXT * DMODEL];
__device__ __half g_wmvh[(size_t)DMODEL * SEXT];
__device__ unsigned g_min_u;

// ---------------- global atomic-min encoding ----------------
__device__ __forceinline__ unsigned enc_min(float f) {
    unsigned u = __float_as_uint(f);
    return (u & 0x80000000u) ? ~u : (u | 0x80000000u);
}
__device__ __forceinline__ float dec_min(unsigned k) {
    return (k & 0x80000000u) ? __uint_as_float(k ^ 0x80000000u)
                             : __uint_as_float(~k);
}
__global__ void init_min_kernel() { g_min_u = 0xFFFFFFFFu; }

// ---------------- helpers ----------------
__device__ __forceinline__ void mma_f16(float* c, const unsigned* a, const unsigned* b) {
    asm volatile(
        "mma.sync.aligned.m16n8k16.row.col.f32.f16.f16.f32 "
        "{%0,%1,%2,%3}, {%4,%5,%6,%7}, {%8,%9}, {%0,%1,%2,%3};\n"
        : "+f"(c[0]), "+f"(c[1]), "+f"(c[2]), "+f"(c[3])
        : "r"(a[0]), "r"(a[1]), "r"(a[2]), "r"(a[3]),
          "r"(b[0]), "r"(b[1]));
}
__device__ __forceinline__ void ldsm4(unsigned& r0, unsigned& r1, unsigned& r2, unsigned& r3,
                                      uint32_t a) {
    asm volatile("ldmatrix.sync.aligned.m8n8.x4.shared.b16 {%0,%1,%2,%3}, [%4];"
                 : "=r"(r0), "=r"(r1), "=r"(r2), "=r"(r3) : "r"(a));
}
__device__ __forceinline__ uint32_t smem_u32(const void* p) {
    uint32_t a;
    asm("{ .reg .u64 t; cvta.to.shared.u64 t, %1; cvt.u32.u64 %0, t; }" : "=r"(a) : "l"(p));
    return a;
}
__device__ __forceinline__ void cp16(uint32_t dst, const void* src) {
    asm volatile("cp.async.cg.shared.global [%0], [%1], 16;" :: "r"(dst), "l"(src));
}
#define CP_COMMIT() asm volatile("cp.async.commit_group;" ::: "memory")
#define CP_WAIT2()  asm volatile("cp.async.wait_group 2;" ::: "memory")

// unpack 8 halves (one uint4) -> 8 floats at dst
__device__ __forceinline__ void h8_to_f8(uint4 u, float* dst) {
    const __half2* hp = (const __half2*)&u;
    float2 f0 = __half22float2(hp[0]);
    float2 f1 = __half22float2(hp[1]);
    float2 f2 = __half22float2(hp[2]);
    float2 f3 = __half22float2(hp[3]);
    *(float4*)dst       = make_float4(f0.x, f0.y, f1.x, f1.y);
    *(float4*)(dst + 4) = make_float4(f2.x, f2.y, f3.x, f3.y);
}

// ---------------- fused fp32->fp16 conversions ----------------
__global__ void __launch_bounds__(256) cvt_act_kernel(
    const float4* __restrict__ s0, const float4* __restrict__ s1, const float4* __restrict__ s2,
    __half2* __restrict__ d0, __half2* __restrict__ d1, __half2* __restrict__ d2, int n4)
{
    const int z = blockIdx.y;
    const float4* s = (z == 0) ? s0 : (z == 1) ? s1 : s2;
    __half2* d = (z == 0) ? d0 : (z == 1) ? d1 : d2;
    int i = blockIdx.x * 256 + threadIdx.x;
    if (i < n4) {
        float4 v = s[i];
        d[2 * i]     = __float22half2_rn(make_float2(v.x, v.y));
        d[2 * i + 1] = __float22half2_rn(make_float2(v.z, v.w));
    }
}

__global__ void __launch_bounds__(256) cvt_w_kernel(
    const float4* __restrict__ s0, const float4* __restrict__ s1,
    const float4* __restrict__ s2, const float4* __restrict__ s3,
    const float4* __restrict__ s4, const float4* __restrict__ s5,
    __half2* __restrict__ d0, __half2* __restrict__ d1,
    __half2* __restrict__ d2, __half2* __restrict__ d3,
    __half2* __restrict__ d4, __half2* __restrict__ d5,
    int nbig, int nsmall)
{
    const int z = blockIdx.y;
    const float4* sa[6] = { s0, s1, s2, s3, s4, s5 };
    __half2* da[6] = { d0, d1, d2, d3, d4, d5 };
    const int n4 = (z < 4) ? nbig : nsmall;
    int i = blockIdx.x * 256 + threadIdx.x;
    if (i < n4) {
        float4 v = sa[z][i];
        da[z][2 * i]     = __float22half2_rn(make_float2(v.x, v.y));
        da[z][2 * i + 1] = __float22half2_rn(make_float2(v.z, v.w));
    }
}

// =====================================================================
// Shared GEMM body: C[M,N] = A[M,K] * B[N,K]^T (+ Res fp32).
// BM=128, BK=64, BN in {128,64}. 256 thr, 8 warps (4Mx2N), 3-stage cp.async.
// =====================================================================
template<int BN, bool RES, bool OUTH>
__device__ __forceinline__ void gemm_body(
    const __half* __restrict__ A, const __half* __restrict__ B,
    const float* __restrict__ Res, void* __restrict__ Cv, int K, int N,
    char* smc, int bm, int bn)
{
    constexpr int ABYTES = 128 * 128;
    constexpr int BBYTES = BN * 128;
    constexpr int STB    = ABYTES + BBYTES;
    constexpr int BCH    = BN * 8 / 256;
    constexpr int WNT    = BN / 2;
    constexpr int NT     = WNT / 8;
    constexpr int MT     = 2;

    const uint32_t sbase = smem_u32(smc);
    const int tid  = threadIdx.x;
    const int lane = tid & 31;
    const int wid  = tid >> 5;
    const int wm   = wid & 3;
    const int wn   = wid >> 2;

    const int mA = tid >> 3;
    const int cA = tid & 7;
    const int nk = K / 64;

    auto issue = [&](int kt, int s) {
        const uint32_t so = (uint32_t)s * STB;
        const int k0 = kt * 64;
#pragma unroll
        for (int i = 0; i < 4; i++) {
            const int m = mA + 32 * i;
            const uint32_t dst = sbase + so + (uint32_t)m * 128u + (uint32_t)((cA ^ (m & 7)) << 4);
            cp16(dst, A + (size_t)(bm + m) * K + k0 + cA * 8);
        }
#pragma unroll
        for (int i = 0; i < BCH; i++) {
            const int m = mA + 32 * i;
            const uint32_t dst = sbase + so + (uint32_t)ABYTES
                               + (uint32_t)m * 128u + (uint32_t)((cA ^ (m & 7)) << 4);
            cp16(dst, B + (size_t)(bn + m) * K + k0 + cA * 8);
        }
    };

    float acc[MT][NT][4];
#pragma unroll
    for (int i = 0; i < MT; i++)
#pragma unroll
        for (int j = 0; j < NT; j++)
#pragma unroll
            for (int t = 0; t < 4; t++) acc[i][j][t] = 0.f;

    issue(0, 0); CP_COMMIT();
    if (nk > 1) issue(1, 1);
    CP_COMMIT();

    uint32_t aaddr[MT];
    {
        const int g = lane >> 3;
        const int arow_in = (g & 1) * 8 + (lane & 7);
        const uint32_t apar = (uint32_t)(g >> 1);
#pragma unroll
        for (int i = 0; i < MT; i++) {
            const int row = wm * 32 + i * 16 + arow_in;
            aaddr[i] = (uint32_t)row * 128u + ((((uint32_t)row & 7u) ^ apar) << 4);
        }
    }
    uint32_t baddr[NT / 2];
    {
        const int g = lane >> 3;
        const int nrow_in = ((g >> 1) & 1) * 8 + (lane & 7);
        const uint32_t bpar = (uint32_t)(g & 1);
#pragma unroll
        for (int jp = 0; jp < NT / 2; jp++) {
            const int n = wn * WNT + jp * 16 + nrow_in;
            baddr[jp] = (uint32_t)n * 128u + ((((uint32_t)n & 7u) ^ bpar) << 4);
        }
    }

    for (int kt = 0; kt < nk; kt++) {
        const int s = kt % 3;
        if (kt + 2 < nk) issue(kt + 2, (kt + 2) % 3);
        CP_COMMIT();
        CP_WAIT2();
        __syncthreads();

        const uint32_t sa = sbase + (uint32_t)s * STB;
        const uint32_t sb = sa + ABYTES;

#pragma unroll
        for (int ks = 0; ks < 4; ks++) {
            const uint32_t kx = (uint32_t)(2 * ks) << 4;
            unsigned af[MT][4], bf[NT][2];
#pragma unroll
            for (int i = 0; i < MT; i++)
                ldsm4(af[i][0], af[i][1], af[i][2], af[i][3], sa + (aaddr[i] ^ kx));
#pragma unroll
            for (int jp = 0; jp < NT / 2; jp++)
                ldsm4(bf[2 * jp][0], bf[2 * jp][1], bf[2 * jp + 1][0], bf[2 * jp + 1][1],
                      sb + (baddr[jp] ^ kx));
#pragma unroll
            for (int i = 0; i < MT; i++)
#pragma unroll
                for (int j = 0; j < NT; j++)
                    mma_f16(acc[i][j], af[i], bf[j]);
        }
        __syncthreads();
    }

#pragma unroll
    for (int i = 0; i < MT; i++) {
#pragma unroll
        for (int j = 0; j < NT; j++) {
            const int r0 = bm + wm * 32 + i * 16 + (lane >> 2);
            const int c0 = bn + wn * WNT + j * 8 + (lane & 3) * 2;
            float2 v0 = make_float2(acc[i][j][0], acc[i][j][1]);
            float2 v1 = make_float2(acc[i][j][2], acc[i][j][3]);
            if (OUTH) {
                __half* Co = (__half*)Cv;
                *(__half2*)&Co[(size_t)r0 * N + c0]       = __floats2half2_rn(v0.x, v0.y);
                *(__half2*)&Co[(size_t)(r0 + 8) * N + c0] = __floats2half2_rn(v1.x, v1.y);
            } else {
                float* Cf = (float*)Cv;
                if (RES) {
                    float2 ra = *(const float2*)&Res[(size_t)r0 * N + c0];
                    float2 rb = *(const float2*)&Res[(size_t)(r0 + 8) * N + c0];
                    v0.x += ra.x; v0.y += ra.y;
                    v1.x += rb.x; v1.y += rb.y;
                }
                *(float2*)&Cf[(size_t)r0 * N + c0] = v0;
                *(float2*)&Cf[(size_t)(r0 + 8) * N + c0] = v1;
            }
        }
    }
}

// ---- fused 3-way projection GEMM (grid.z selects q/k/v) ----
__global__ void __launch_bounds__(256, 2) gemm_proj3(
    const __half* A0, const __half* A1, const __half* A2,
    const __half* B0, const __half* B1, const __half* B2,
    __half* C0, __half* C1, __half* C2)
{
    extern __shared__ char smc[];
    const int z = blockIdx.z;
    const __half* A = (z == 0) ? A0 : (z == 1) ? A1 : A2;
    const __half* B = (z == 0) ? B0 : (z == 1) ? B1 : B2;
    __half* C = (z == 0) ? C0 : (z == 1) ? C1 : C2;
    gemm_body<128, false, true>(A, B, nullptr, C, DMODEL, DMODEL,
                                smc, blockIdx.y * 128, blockIdx.x * 128);
}

// ---- FC GEMM: x = attn_out @ Wfc^T + q (fp32 out) ----
__global__ void __launch_bounds__(256, 2) gemm_fc(
    const __half* __restrict__ A, const __half* __restrict__ B,
    const float* __restrict__ Res, float* __restrict__ C)
{
    extern __shared__ char smc[];
    gemm_body<128, true, false>(A, B, Res, C, DMODEL, DMODEL,
                                smc, blockIdx.y * 128, blockIdx.x * 128);
}

// ---- final GEMM: out = x + a @ Wmv^T (K=64) ----
__global__ void __launch_bounds__(256, 2) gemm_final(
    const __half* __restrict__ A, const __half* __restrict__ B,
    const float* __restrict__ Res, float* __restrict__ C)
{
    extern __shared__ char smc[];
    gemm_body<128, true, false>(A, B, Res, C, SEXT, DMODEL,
                                smc, blockIdx.y * 128, blockIdx.x * 128);
}

// =====================================================================
// Fused xa GEMM + ExternalAttention normalization (R11 version).
// xa = g_xh @ Wmk^T (128x64 tile/CTA, K=1024, 3-stage pipeline), then
// softmax over modal rows + renorm over S -> g_ah (fp16).
// =====================================================================
__global__ void __launch_bounds__(256, 2) gemm_xa_ext(
    const __half* __restrict__ A, const __half* __restrict__ B)
{
    constexpr int BN     = 64;
    constexpr int ABYTES = 128 * 128;
    constexpr int BBYTES = BN * 128;
    constexpr int STB    = ABYTES + BBYTES;
    constexpr int BCH    = 2;
    constexpr int WNT    = 32;
    constexpr int NT     = 4;
    constexpr int MT     = 2;
    constexpr int K      = DMODEL;
    constexpr int TP     = 66;

    extern __shared__ char smc[];
    const uint32_t sbase = smem_u32(smc);

    const int tid  = threadIdx.x;
    const int lane = tid & 31;
    const int wid  = tid >> 5;
    const int wm   = wid & 3;
    const int wn   = wid >> 2;
    const int bm   = blockIdx.y * 128;

    const int mA = tid >> 3;
    const int cA = tid & 7;
    constexpr int nk = K / 64;   // 16

    auto issue = [&](int kt, int s) {
        const uint32_t so = (uint32_t)s * STB;
        const int k0 = kt * 64;
#pragma unroll
        for (int i = 0; i < 4; i++) {
            const int m = mA + 32 * i;
            const uint32_t dst = sbase + so + (uint32_t)m * 128u + (uint32_t)((cA ^ (m & 7)) << 4);
            cp16(dst, A + (size_t)(bm + m) * K + k0 + cA * 8);
        }
#pragma unroll
        for (int i = 0; i < BCH; i++) {
            const int m = mA + 32 * i;
            const uint32_t dst = sbase + so + (uint32_t)ABYTES
                               + (uint32_t)m * 128u + (uint32_t)((cA ^ (m & 7)) << 4);
            cp16(dst, B + (size_t)m * K + k0 + cA * 8);
        }
    };

    float acc[MT][NT][4];
#pragma unroll
    for (int i = 0; i < MT; i++)
#pragma unroll
        for (int j = 0; j < NT; j++)
#pragma unroll
            for (int t = 0; t < 4; t++) acc[i][j][t] = 0.f;

    issue(0, 0); CP_COMMIT();
    issue(1, 1); CP_COMMIT();

    uint32_t aaddr[MT];
    {
        const int g = lane >> 3;
        const int arow_in = (g & 1) * 8 + (lane & 7);
        const uint32_t apar = (uint32_t)(g >> 1);
#pragma unroll
        for (int i = 0; i < MT; i++) {
            const int row = wm * 32 + i * 16 + arow_in;
            aaddr[i] = (uint32_t)row * 128u + ((((uint32_t)row & 7u) ^ apar) << 4);
        }
    }
    uint32_t baddr[NT / 2];
    {
        const int g = lane >> 3;
        const int nrow_in = ((g >> 1) & 1) * 8 + (lane & 7);
        const uint32_t bpar = (uint32_t)(g & 1);
#pragma unroll
        for (int jp = 0; jp < NT / 2; jp++) {
            const int n = wn * WNT + jp * 16 + nrow_in;
            baddr[jp] = (uint32_t)n * 128u + ((((uint32_t)n & 7u) ^ bpar) << 4);
        }
    }

    for (int kt = 0; kt < nk; kt++) {
        const int s = kt % 3;
        if (kt + 2 < nk) issue(kt + 2, (kt + 2) % 3);
        CP_COMMIT();
        CP_WAIT2();
        __syncthreads();

        const uint32_t sa = sbase + (uint32_t)s * STB;
        const uint32_t sb = sa + ABYTES;

#pragma unroll
        for (int ks = 0; ks < 4; ks++) {
            const uint32_t kx = (uint32_t)(2 * ks) << 4;
            unsigned af[MT][4], bf[NT][2];
#pragma unroll
            for (int i = 0; i < MT; i++)
                ldsm4(af[i][0], af[i][1], af[i][2], af[i][3], sa + (aaddr[i] ^ kx));
#pragma unroll
            for (int jp = 0; jp < NT / 2; jp++)
                ldsm4(bf[2 * jp][0], bf[2 * jp][1], bf[2 * jp + 1][0], bf[2 * jp + 1][1],
                      sb + (baddr[jp] ^ kx));
#pragma unroll
            for (int i = 0; i < MT; i++)
#pragma unroll
                for (int j = 0; j < NT; j++)
                    mma_f16(acc[i][j], af[i], bf[j]);
        }
        __syncthreads();
    }

    // ---- fused ext-attention epilogue ----
    float* tile = (float*)smc;               // [128][TP]
    float* rsum = tile + 128 * TP;           // [128]
#pragma unroll
    for (int i = 0; i < MT; i++) {
#pragma unroll
        for (int j = 0; j < NT; j++) {
            const int rl = wm * 32 + i * 16 + (lane >> 2);
            const int cl = wn * WNT + j * 8 + (lane & 3) * 2;
            *(float2*)&tile[rl * TP + cl]       = make_float2(acc[i][j][0], acc[i][j][1]);
            *(float2*)&tile[(rl + 8) * TP + cl] = make_float2(acc[i][j][2], acc[i][j][3]);
        }
    }
    __syncthreads();

    for (int p = tid; p < 16 * SEXT; p += 256) {
        const int bl = p >> 6, s = p & 63;
        float* col = &tile[(bl * 8) * TP + s];
        float mx = col[0];
#pragma unroll
        for (int m = 1; m < MODAL; m++) mx = fmaxf(mx, col[m * TP]);
        float sum = 0.f;
        float e[MODAL];
#pragma unroll
        for (int m = 0; m < MODAL; m++) { e[m] = expf(col[m * TP] - mx); sum += e[m]; }
        const float is = 1.f / sum;
#pragma unroll
        for (int m = 0; m < MODAL; m++) col[m * TP] = e[m] * is;
    }
    __syncthreads();

    for (int r = tid; r < 128; r += 256) {
        float t = 0.f;
        const float* row = &tile[r * TP];
#pragma unroll
        for (int s = 0; s < SEXT; s++) t += row[s];
        rsum[r] = 1.f / t;
    }
    __syncthreads();

    for (int idx = tid; idx < 128 * (SEXT / 2); idx += 256) {
        const int r = idx >> 5, sp = (idx & 31) * 2;
        const float rs = rsum[r];
        *(__half2*)&g_ah[(size_t)(bm + r) * SEXT + sp] =
            __floats2half2_rn(tile[r * TP + sp] * rs, tile[r * TP + sp + 1] * rs);
    }
}

// ---------------- attention pass A: scores + global min (fp16 inputs) ----------------
constexpr int QPAD = DMODEL + 4;

extern __shared__ float dynsmem[];

__global__ void __launch_bounds__(256) attn_scores_kernel() {
    float* qs = dynsmem;
    float* ks = dynsmem + MODAL * QPAD;
    const int b = blockIdx.x, tid = threadIdx.x;
    const uint4* qg = (const uint4*)(g_qph + (size_t)b * MODAL * DMODEL);
    const uint4* kg = (const uint4*)(g_kph + (size_t)b * MODAL * DMODEL);
    for (int i = tid; i < MODAL * DMODEL / 8; i += 256) {
        int m = i >> 7, c = i & 127;
        h8_to_f8(qg[i], &qs[m * QPAD + c * 8]);
        h8_to_f8(kg[i], &ks[m * QPAD + c * 8]);
    }
    __syncthreads();

    float lmin = 3.4e38f;
    for (int s = tid; s < NHEAD * MODAL * MODAL; s += 256) {
        int h = s >> 6, m = (s >> 3) & 7, n = s & 7;
        const float4* qr = (const float4*)&qs[m * QPAD + h * DK];
        const float4* kr = (const float4*)&ks[n * QPAD + h * DK];
        float acc = 0.f;
#pragma unroll
        for (int d = 0; d < 16; d++) {
            float4 a = qr[d], c = kr[d];
            acc += a.x * c.x + a.y * c.y + a.z * c.z + a.w * c.w;
        }
        acc *= 0.125f;
        g_scores[(size_t)b * 1024 + s] = acc;
        lmin = fminf(lmin, acc);
    }
#pragma unroll
    for (int o = 16; o; o >>= 1) lmin = fminf(lmin, __shfl_xor_sync(0xffffffffu, lmin, o));
    __shared__ float wmn[8];
    if ((tid & 31) == 0) wmn[tid >> 5] = lmin;
    __syncthreads();
    if (tid == 0) {
        float m = wmn[0];
#pragma unroll
        for (int i = 1; i < 8; i++) m = fminf(m, wmn[i]);
        atomicMin(&g_min_u, enc_min(m));
    }
}

// ---------------- attention pass B (fp16 v input, fp16 output) ----------------
__global__ void __launch_bounds__(256) attn_out_kernel() {
    __shared__ float vs[MODAL * QPAD];
    __shared__ float sc[NHEAD * 64];
    __shared__ float aw[NHEAD * 64];
    const int b = blockIdx.x, tid = threadIdx.x;
    const float inv = 1.f / fabsf(dec_min(g_min_u));

    const uint4* vg = (const uint4*)(g_vph + (size_t)b * MODAL * DMODEL);
    for (int i = tid; i < MODAL * DMODEL / 8; i += 256) {
        int m = i >> 7, c = i & 127;
        h8_to_f8(vg[i], &vs[m * QPAD + c * 8]);
    }
    for (int i = tid; i < 1024; i += 256)
        sc[i] = g_scores[(size_t)b * 1024 + i] * inv;
    __syncthreads();

    if (tid < 128) {
        int h = tid >> 3, m = tid & 7;
        float r[8]; float ss = 0.f;
#pragma unroll
        for (int n = 0; n < 8; n++) { r[n] = sc[h * 64 + m * 8 + n]; ss += r[n] * r[n]; }
        float nrm = fmaxf(sqrtf(ss), 1e-12f);
        float rn = 1.f / nrm;
        float mx = -3.4e38f;
#pragma unroll
        for (int n = 0; n < 8; n++) { r[n] *= rn; mx = fmaxf(mx, r[n]); }
        float sum = 0.f;
#pragma unroll
        for (int n = 0; n < 8; n++) { r[n] = expf(r[n] - mx); sum += r[n]; }
        float is = 1.f / sum;
#pragma unroll
        for (int n = 0; n < 8; n++) aw[h * 64 + m * 8 + n] = r[n] * is;
    }
    __syncthreads();

    __half* og = g_atth + (size_t)b * MODAL * DMODEL;
    for (int o = tid; o < MODAL * DMODEL; o += 256) {
        int m = o >> 10, col = o & 1023, h = col >> 6;
        float acc = 0.f;
#pragma unroll
        for (int n = 0; n < 8; n++) acc += aw[h * 64 + m * 8 + n] * vs[n * QPAD + col];
        og[o] = __float2half_rn(acc);
    }
}

// ---------------- LayerNorm: fp32 x in -> fp32 out + fp16 copy ----------------
__global__ void __launch_bounds__(256) ln_kernel(
    const float* __restrict__ gamma, const float* __restrict__ beta,
    float* __restrict__ out)
{
    const int wid = threadIdx.x >> 5, lane = threadIdx.x & 31;
    const size_t row = (size_t)blockIdx.x * 8 + wid;
    const float4* xr = (const float4*)(g_x + row * DMODEL);
    float4 v[8];
    float s = 0.f, s2 = 0.f;
#pragma unroll
    for (int i = 0; i < 8; i++) {
        v[i] = xr[lane + 32 * i];
        s += v[i].x + v[i].y + v[i].z + v[i].w;
        s2 += v[i].x * v[i].x + v[i].y * v[i].y + v[i].z * v[i].z + v[i].w * v[i].w;
    }
#pragma unroll
    for (int o = 16; o; o >>= 1) {
        s += __shfl_xor_sync(0xffffffffu, s, o);
        s2 += __shfl_xor_sync(0xffffffffu, s2, o);
    }
    const float mu = s * (1.f / DMODEL);
    const float var = fmaxf(s2 * (1.f / DMODEL) - mu * mu, 0.f);
    const float rs = rsqrtf(var + 1e-10f);
    float4* orow = (float4*)(out + row * DMODEL);
    __half2* hrow = (__half2*)(g_xh + row * DMODEL);
    const float4* gm = (const float4*)gamma;
    const float4* bt = (const float4*)beta;
#pragma unroll
    for (int i = 0; i < 8; i++) {
        int c4 = lane + 32 * i;
        float4 g = gm[c4], bb = bt[c4], x = v[i], r;
        r.x = (x.x - mu) * rs * g.x + bb.x;
        r.y = (x.y - mu) * rs * g.y + bb.y;
        r.z = (x.z - mu) * rs * g.z + bb.z;
        r.w = (x.w - mu) * rs * g.w + bb.w;
        orow[c4] = r;
        hrow[2 * c4]     = __float22half2_rn(make_float2(r.x, r.y));
        hrow[2 * c4 + 1] = __float22half2_rn(make_float2(r.z, r.w));
    }
}

// ---------------- launch ----------------
extern "C" void kernel_launch(void* const* d_in, const int* in_sizes, int n_in,
                              void* d_out, int out_size)
{
    const float* q     = (const float*)d_in[0];
    const float* k     = (const float*)d_in[1];
    const float* v     = (const float*)d_in[2];
    const float* Wq    = (const float*)d_in[3];
    const float* Wk    = (const float*)d_in[4];
    const float* Wv    = (const float*)d_in[5];
    const float* Wfc   = (const float*)d_in[6];
    const float* gamma = (const float*)d_in[7];
    const float* beta  = (const float*)d_in[8];
    const float* Wmk   = (const float*)d_in[9];
    const float* Wmv   = (const float*)d_in[10];
    float* out = (float*)d_out;

    float *px;
    __half *pqh, *pkh, *pvh, *pqph, *pkph, *pvph, *patth, *pxh, *pah;
    __half *pwqh, *pwkh, *pwvh, *pwfch, *pwmkh, *pwmvh;
    cudaGetSymbolAddress((void**)&px,    g_x);
    cudaGetSymbolAddress((void**)&pqh,   g_qh);
    cudaGetSymbolAddress((void**)&pkh,   g_kh);
    cudaGetSymbolAddress((void**)&pvh,   g_vh);
    cudaGetSymbolAddress((void**)&pqph,  g_qph);
    cudaGetSymbolAddress((void**)&pkph,  g_kph);
    cudaGetSymbolAddress((void**)&pvph,  g_vph);
    cudaGetSymbolAddress((void**)&patth, g_atth);
    cudaGetSymbolAddress((void**)&pxh,   g_xh);
    cudaGetSymbolAddress((void**)&pah,   g_ah);
    cudaGetSymbolAddress((void**)&pwqh,  g_wqh);
    cudaGetSymbolAddress((void**)&pwkh,  g_wkh);
    cudaGetSymbolAddress((void**)&pwvh,  g_wvh);
    cudaGetSymbolAddress((void**)&pwfch, g_wfch);
    cudaGetSymbolAddress((void**)&pwmkh, g_wmkh);
    cudaGetSymbolAddress((void**)&pwmvh, g_wmvh);

    const int smem_sc = 2 * MODAL * QPAD * (int)sizeof(float);
    cudaFuncSetAttribute(attn_scores_kernel,
                         cudaFuncAttributeMaxDynamicSharedMemorySize, smem_sc);

    const int smem128 = 3 * (128 * 128 + 128 * 128);  // 98304 B
    const int smem64  = 3 * (128 * 128 + 64 * 128);   // 73728 B
    cudaFuncSetAttribute(gemm_proj3,
                         cudaFuncAttributeMaxDynamicSharedMemorySize, smem128);
    cudaFuncSetAttribute(gemm_fc,
                         cudaFuncAttributeMaxDynamicSharedMemorySize, smem128);
    cudaFuncSetAttribute(gemm_final,
                         cudaFuncAttributeMaxDynamicSharedMemorySize, smem128);
    cudaFuncSetAttribute(gemm_xa_ext,
                         cudaFuncAttributeMaxDynamicSharedMemorySize, smem64);

    init_min_kernel<<<1, 1>>>();

    const int a4 = ROWS * DMODEL / 4;
    const int w4 = DMODEL * DMODEL / 4;
    const int s4 = SEXT * DMODEL / 4;

    // fused conversions: activations (3 slots), weights (6 slots)
    cvt_act_kernel<<<dim3((a4 + 255) / 256, 3), 256>>>(
        (const float4*)q, (const float4*)k, (const float4*)v,
        (__half2*)pqh, (__half2*)pkh, (__half2*)pvh, a4);
    cvt_w_kernel<<<dim3((w4 + 255) / 256, 6), 256>>>(
        (const float4*)Wq, (const float4*)Wk, (const float4*)Wv, (const float4*)Wfc,
        (const float4*)Wmk, (const float4*)Wmv,
        (__half2*)pwqh, (__half2*)pwkh, (__half2*)pwvh, (__half2*)pwfch,
        (__half2*)pwmkh, (__half2*)pwmvh, w4, s4);

    // fused q/k/v projections
    gemm_proj3<<<dim3(DMODEL / 128, ROWS / 128, 3), 256, smem128>>>(
        pqh, pkh, pvh, pwqh, pwkh, pwvh, pqph, pkph, pvph);

    attn_scores_kernel<<<BSZ, 256, smem_sc>>>();
    attn_out_kernel<<<BSZ, 256>>>();

    // x = attn_out @ Wfc^T + q (fp32 residual)
    gemm_fc<<<dim3(DMODEL / 128, ROWS / 128), 256, smem128>>>(patth, pwfch, q, px);

    // LayerNorm -> out (fp32) + g_xh (fp16)
    ln_kernel<<<ROWS / 8, 256>>>(gamma, beta, out);

    // fused: xa = x @ Wmk^T + softmax/renorm -> g_ah (fp16)
    gemm_xa_ext<<<dim3(1, ROWS / 128), 256, smem64>>>(pxh, pwmkh);

    // out = x + a @ Wmv^T (K=64)
    gemm_final<<<dim3(DMODEL / 128, ROWS / 128), 256, smem128>>>(pah, pwmvh, out, out);
}

// round 14
// speedup vs baseline: 1.1423x; 1.0067x over previous
#include <cuda_runtime.h>
#include <cuda_fp16.h>
#include <cstdint>

// ---------------- problem constants ----------------
constexpr int MODAL  = 8;
constexpr int DMODEL = 1024;
constexpr int NHEAD  = 16;
constexpr int DK     = 64;
constexpr int SEXT   = 64;
constexpr int BSZ    = 4096;
constexpr int ROWS   = BSZ * MODAL;   // 32768

// ---------------- scratch (device globals) ----------------
__device__ float g_x  [(size_t)ROWS * DMODEL];
__device__ float g_scores[(size_t)BSZ * NHEAD * MODAL * MODAL];
// fp16 operands
__device__ __half g_qh  [(size_t)ROWS * DMODEL];
__device__ __half g_kh  [(size_t)ROWS * DMODEL];
__device__ __half g_vh  [(size_t)ROWS * DMODEL];
__device__ __half g_qph [(size_t)ROWS * DMODEL];
__device__ __half g_kph [(size_t)ROWS * DMODEL];
__device__ __half g_vph [(size_t)ROWS * DMODEL];
__device__ __half g_atth[(size_t)ROWS * DMODEL];
__device__ __half g_xh  [(size_t)ROWS * DMODEL];
__device__ __half g_ah  [(size_t)ROWS * SEXT];
__device__ __half g_wqh [(size_t)DMODEL * DMODEL];
__device__ __half g_wkh [(size_t)DMODEL * DMODEL];
__device__ __half g_wvh [(size_t)DMODEL * DMODEL];
__device__ __half g_wfch[(size_t)DMODEL * DMODEL];
__device__ __half g_wmkh[(size_t)SEXT * DMODEL];
__device__ __half g_wmvh[(size_t)DMODEL * SEXT];
__device__ unsigned g_min_u;

// ---------------- global atomic-min encoding ----------------
__device__ __forceinline__ unsigned enc_min(float f) {
    unsigned u = __float_as_uint(f);
    return (u & 0x80000000u) ? ~u : (u | 0x80000000u);
}
__device__ __forceinline__ float dec_min(unsigned k) {
    return (k & 0x80000000u) ? __uint_as_float(k ^ 0x80000000u)
                             : __uint_as_float(~k);
}
__global__ void init_min_kernel() { g_min_u = 0xFFFFFFFFu; }

// ---------------- helpers ----------------
__device__ __forceinline__ void mma_f16(float* c, const unsigned* a, const unsigned* b) {
    asm volatile(
        "mma.sync.aligned.m16n8k16.row.col.f32.f16.f16.f32 "
        "{%0,%1,%2,%3}, {%4,%5,%6,%7}, {%8,%9}, {%0,%1,%2,%3};\n"
        : "+f"(c[0]), "+f"(c[1]), "+f"(c[2]), "+f"(c[3])
        : "r"(a[0]), "r"(a[1]), "r"(a[2]), "r"(a[3]),
          "r"(b[0]), "r"(b[1]));
}
__device__ __forceinline__ void ldsm4(unsigned& r0, unsigned& r1, unsigned& r2, unsigned& r3,
                                      uint32_t a) {
    asm volatile("ldmatrix.sync.aligned.m8n8.x4.shared.b16 {%0,%1,%2,%3}, [%4];"
                 : "=r"(r0), "=r"(r1), "=r"(r2), "=r"(r3) : "r"(a));
}
__device__ __forceinline__ uint32_t smem_u32(const void* p) {
    uint32_t a;
    asm("{ .reg .u64 t; cvta.to.shared.u64 t, %1; cvt.u32.u64 %0, t; }" : "=r"(a) : "l"(p));
    return a;
}
__device__ __forceinline__ void cp16(uint32_t dst, const void* src) {
    asm volatile("cp.async.cg.shared.global [%0], [%1], 16;" :: "r"(dst), "l"(src));
}
#define CP_COMMIT() asm volatile("cp.async.commit_group;" ::: "memory")
#define CP_WAIT1()  asm volatile("cp.async.wait_group 1;" ::: "memory")

// unpack 8 halves (one uint4) -> 8 floats at dst
__device__ __forceinline__ void h8_to_f8(uint4 u, float* dst) {
    const __half2* hp = (const __half2*)&u;
    float2 f0 = __half22float2(hp[0]);
    float2 f1 = __half22float2(hp[1]);
    float2 f2 = __half22float2(hp[2]);
    float2 f3 = __half22float2(hp[3]);
    *(float4*)dst       = make_float4(f0.x, f0.y, f1.x, f1.y);
    *(float4*)(dst + 4) = make_float4(f2.x, f2.y, f3.x, f3.y);
}

// ---------------- fused fp32->fp16 conversions ----------------
__global__ void __launch_bounds__(256) cvt_act_kernel(
    const float4* __restrict__ s0, const float4* __restrict__ s1, const float4* __restrict__ s2,
    __half2* __restrict__ d0, __half2* __restrict__ d1, __half2* __restrict__ d2, int n4)
{
    const int z = blockIdx.y;
    const float4* s = (z == 0) ? s0 : (z == 1) ? s1 : s2;
    __half2* d = (z == 0) ? d0 : (z == 1) ? d1 : d2;
    int i = blockIdx.x * 256 + threadIdx.x;
    if (i < n4) {
        float4 v = s[i];
        d[2 * i]     = __float22half2_rn(make_float2(v.x, v.y));
        d[2 * i + 1] = __float22half2_rn(make_float2(v.z, v.w));
    }
}

__global__ void __launch_bounds__(256) cvt_w_kernel(
    const float4* __restrict__ s0, const float4* __restrict__ s1,
    const float4* __restrict__ s2, const float4* __restrict__ s3,
    const float4* __restrict__ s4, const float4* __restrict__ s5,
    __half2* __restrict__ d0, __half2* __restrict__ d1,
    __half2* __restrict__ d2, __half2* __restrict__ d3,
    __half2* __restrict__ d4, __half2* __restrict__ d5,
    int nbig, int nsmall)
{
    const int z = blockIdx.y;
    const float4* sa[6] = { s0, s1, s2, s3, s4, s5 };
    __half2* da[6] = { d0, d1, d2, d3, d4, d5 };
    const int n4 = (z < 4) ? nbig : nsmall;
    int i = blockIdx.x * 256 + threadIdx.x;
    if (i < n4) {
        float4 v = sa[z][i];
        da[z][2 * i]     = __float22half2_rn(make_float2(v.x, v.y));
        da[z][2 * i + 1] = __float22half2_rn(make_float2(v.z, v.w));
    }
}

// =====================================================================
// Shared GEMM body: C[M,N] = A[M,K] * B[N,K]^T (+ Res fp32).
// BM=128, BK=64, BN in {128,64}. 256 thr, 8 warps (4Mx2N).
// 3-stage cp.async pipeline with ONE __syncthreads per k-tile:
//   top of iter kt: wait_group 1 (group kt complete) -> sync ->
//   issue group kt+2 into stage (kt+2)%3 == (kt-1)%3 (all reads of that
//   stage finished before this sync) -> compute stage kt%3.
// =====================================================================
template<int BN, bool RES, bool OUTH>
__device__ __forceinline__ void gemm_body(
    const __half* __restrict__ A, const __half* __restrict__ B,
    const float* __restrict__ Res, void* __restrict__ Cv, int K, int N,
    char* smc, int bm, int bn)
{
    constexpr int ABYTES = 128 * 128;
    constexpr int BBYTES = BN * 128;
    constexpr int STB    = ABYTES + BBYTES;
    constexpr int BCH    = BN * 8 / 256;
    constexpr int WNT    = BN / 2;
    constexpr int NT     = WNT / 8;
    constexpr int MT     = 2;

    const uint32_t sbase = smem_u32(smc);
    const int tid  = threadIdx.x;
    const int lane = tid & 31;
    const int wid  = tid >> 5;
    const int wm   = wid & 3;
    const int wn   = wid >> 2;

    const int mA = tid >> 3;
    const int cA = tid & 7;
    const int nk = K / 64;

    auto issue = [&](int kt, int s) {
        const uint32_t so = (uint32_t)s * STB;
        const int k0 = kt * 64;
#pragma unroll
        for (int i = 0; i < 4; i++) {
            const int m = mA + 32 * i;
            const uint32_t dst = sbase + so + (uint32_t)m * 128u + (uint32_t)((cA ^ (m & 7)) << 4);
            cp16(dst, A + (size_t)(bm + m) * K + k0 + cA * 8);
        }
#pragma unroll
        for (int i = 0; i < BCH; i++) {
            const int m = mA + 32 * i;
            const uint32_t dst = sbase + so + (uint32_t)ABYTES
                               + (uint32_t)m * 128u + (uint32_t)((cA ^ (m & 7)) << 4);
            cp16(dst, B + (size_t)(bn + m) * K + k0 + cA * 8);
        }
    };

    float acc[MT][NT][4];
#pragma unroll
    for (int i = 0; i < MT; i++)
#pragma unroll
        for (int j = 0; j < NT; j++)
#pragma unroll
            for (int t = 0; t < 4; t++) acc[i][j][t] = 0.f;

    issue(0, 0); CP_COMMIT();
    if (nk > 1) issue(1, 1);
    CP_COMMIT();

    uint32_t aaddr[MT];
    {
        const int g = lane >> 3;
        const int arow_in = (g & 1) * 8 + (lane & 7);
        const uint32_t apar = (uint32_t)(g >> 1);
#pragma unroll
        for (int i = 0; i < MT; i++) {
            const int row = wm * 32 + i * 16 + arow_in;
            aaddr[i] = (uint32_t)row * 128u + ((((uint32_t)row & 7u) ^ apar) << 4);
        }
    }
    uint32_t baddr[NT / 2];
    {
        const int g = lane >> 3;
        const int nrow_in = ((g >> 1) & 1) * 8 + (lane & 7);
        const uint32_t bpar = (uint32_t)(g & 1);
#pragma unroll
        for (int jp = 0; jp < NT / 2; jp++) {
            const int n = wn * WNT + jp * 16 + nrow_in;
            baddr[jp] = (uint32_t)n * 128u + ((((uint32_t)n & 7u) ^ bpar) << 4);
        }
    }

    for (int kt = 0; kt < nk; kt++) {
        CP_WAIT1();
        __syncthreads();
        if (kt + 2 < nk) issue(kt + 2, (kt + 2) % 3);
        CP_COMMIT();

        const uint32_t sa = sbase + (uint32_t)(kt % 3) * STB;
        const uint32_t sb = sa + ABYTES;

#pragma unroll
        for (int ks = 0; ks < 4; ks++) {
            const uint32_t kx = (uint32_t)(2 * ks) << 4;
            unsigned af[MT][4], bf[NT][2];
#pragma unroll
            for (int i = 0; i < MT; i++)
                ldsm4(af[i][0], af[i][1], af[i][2], af[i][3], sa + (aaddr[i] ^ kx));
#pragma unroll
            for (int jp = 0; jp < NT / 2; jp++)
                ldsm4(bf[2 * jp][0], bf[2 * jp][1], bf[2 * jp + 1][0], bf[2 * jp + 1][1],
                      sb + (baddr[jp] ^ kx));
#pragma unroll
            for (int i = 0; i < MT; i++)
#pragma unroll
                for (int j = 0; j < NT; j++)
                    mma_f16(acc[i][j], af[i], bf[j]);
        }
    }

#pragma unroll
    for (int i = 0; i < MT; i++) {
#pragma unroll
        for (int j = 0; j < NT; j++) {
            const int r0 = bm + wm * 32 + i * 16 + (lane >> 2);
            const int c0 = bn + wn * WNT + j * 8 + (lane & 3) * 2;
            float2 v0 = make_float2(acc[i][j][0], acc[i][j][1]);
            float2 v1 = make_float2(acc[i][j][2], acc[i][j][3]);
            if (OUTH) {
                __half* Co = (__half*)Cv;
                *(__half2*)&Co[(size_t)r0 * N + c0]       = __floats2half2_rn(v0.x, v0.y);
                *(__half2*)&Co[(size_t)(r0 + 8) * N + c0] = __floats2half2_rn(v1.x, v1.y);
            } else {
                float* Cf = (float*)Cv;
                if (RES) {
                    float2 ra = *(const float2*)&Res[(size_t)r0 * N + c0];
                    float2 rb = *(const float2*)&Res[(size_t)(r0 + 8) * N + c0];
                    v0.x += ra.x; v0.y += ra.y;
                    v1.x += rb.x; v1.y += rb.y;
                }
                *(float2*)&Cf[(size_t)r0 * N + c0] = v0;
                *(float2*)&Cf[(size_t)(r0 + 8) * N + c0] = v1;
            }
        }
    }
}

// ---- fused 3-way projection GEMM (grid.z selects q/k/v) ----
__global__ void __launch_bounds__(256, 2) gemm_proj3(
    const __half* A0, const __half* A1, const __half* A2,
    const __half* B0, const __half* B1, const __half* B2,
    __half* C0, __half* C1, __half* C2)
{
    extern __shared__ char smc[];
    const int z = blockIdx.z;
    const __half* A = (z == 0) ? A0 : (z == 1) ? A1 : A2;
    const __half* B = (z == 0) ? B0 : (z == 1) ? B1 : B2;
    __half* C = (z == 0) ? C0 : (z == 1) ? C1 : C2;
    gemm_body<128, false, true>(A, B, nullptr, C, DMODEL, DMODEL,
                                smc, blockIdx.y * 128, blockIdx.x * 128);
}

// ---- FC GEMM: x = attn_out @ Wfc^T + q (fp32 out) ----
__global__ void __launch_bounds__(256, 2) gemm_fc(
    const __half* __restrict__ A, const __half* __restrict__ B,
    const float* __restrict__ Res, float* __restrict__ C)
{
    extern __shared__ char smc[];
    gemm_body<128, true, false>(A, B, Res, C, DMODEL, DMODEL,
                                smc, blockIdx.y * 128, blockIdx.x * 128);
}

// ---- final GEMM: out = x + a @ Wmv^T (K=64) ----
__global__ void __launch_bounds__(256, 2) gemm_final(
    const __half* __restrict__ A, const __half* __restrict__ B,
    const float* __restrict__ Res, float* __restrict__ C)
{
    extern __shared__ char smc[];
    gemm_body<128, true, false>(A, B, Res, C, SEXT, DMODEL,
                                smc, blockIdx.y * 128, blockIdx.x * 128);
}

// =====================================================================
// Fused xa GEMM + ExternalAttention normalization.
// Same single-sync 3-stage pipeline; then softmax over modal rows +
// renorm over S -> g_ah (fp16).
// =====================================================================
__global__ void __launch_bounds__(256, 2) gemm_xa_ext(
    const __half* __restrict__ A, const __half* __restrict__ B)
{
    constexpr int BN     = 64;
    constexpr int ABYTES = 128 * 128;
    constexpr int BBYTES = BN * 128;
    constexpr int STB    = ABYTES + BBYTES;
    constexpr int BCH    = 2;
    constexpr int WNT    = 32;
    constexpr int NT     = 4;
    constexpr int MT     = 2;
    constexpr int K      = DMODEL;
    constexpr int TP     = 66;

    extern __shared__ char smc[];
    const uint32_t sbase = smem_u32(smc);

    const int tid  = threadIdx.x;
    const int lane = tid & 31;
    const int wid  = tid >> 5;
    const int wm   = wid & 3;
    const int wn   = wid >> 2;
    const int bm   = blockIdx.y * 128;

    const int mA = tid >> 3;
    const int cA = tid & 7;
    constexpr int nk = K / 64;   // 16

    auto issue = [&](int kt, int s) {
        const uint32_t so = (uint32_t)s * STB;
        const int k0 = kt * 64;
#pragma unroll
        for (int i = 0; i < 4; i++) {
            const int m = mA + 32 * i;
            const uint32_t dst = sbase + so + (uint32_t)m * 128u + (uint32_t)((cA ^ (m & 7)) << 4);
            cp16(dst, A + (size_t)(bm + m) * K + k0 + cA * 8);
        }
#pragma unroll
        for (int i = 0; i < BCH; i++) {
            const int m = mA + 32 * i;
            const uint32_t dst = sbase + so + (uint32_t)ABYTES
                               + (uint32_t)m * 128u + (uint32_t)((cA ^ (m & 7)) << 4);
            cp16(dst, B + (size_t)m * K + k0 + cA * 8);
        }
    };

    float acc[MT][NT][4];
#pragma unroll
    for (int i = 0; i < MT; i++)
#pragma unroll
        for (int j = 0; j < NT; j++)
#pragma unroll
            for (int t = 0; t < 4; t++) acc[i][j][t] = 0.f;

    issue(0, 0); CP_COMMIT();
    issue(1, 1); CP_COMMIT();

    uint32_t aaddr[MT];
    {
        const int g = lane >> 3;
        const int arow_in = (g & 1) * 8 + (lane & 7);
        const uint32_t apar = (uint32_t)(g >> 1);
#pragma unroll
        for (int i = 0; i < MT; i++) {
            const int row = wm * 32 + i * 16 + arow_in;
            aaddr[i] = (uint32_t)row * 128u + ((((uint32_t)row & 7u) ^ apar) << 4);
        }
    }
    uint32_t baddr[NT / 2];
    {
        const int g = lane >> 3;
        const int nrow_in = ((g >> 1) & 1) * 8 + (lane & 7);
        const uint32_t bpar = (uint32_t)(g & 1);
#pragma unroll
        for (int jp = 0; jp < NT / 2; jp++) {
            const int n = wn * WNT + jp * 16 + nrow_in;
            baddr[jp] = (uint32_t)n * 128u + ((((uint32_t)n & 7u) ^ bpar) << 4);
        }
    }

    for (int kt = 0; kt < nk; kt++) {
        CP_WAIT1();
        __syncthreads();
        if (kt + 2 < nk) issue(kt + 2, (kt + 2) % 3);
        CP_COMMIT();

        const uint32_t sa = sbase + (uint32_t)(kt % 3) * STB;
        const uint32_t sb = sa + ABYTES;

#pragma unroll
        for (int ks = 0; ks < 4; ks++) {
            const uint32_t kx = (uint32_t)(2 * ks) << 4;
            unsigned af[MT][4], bf[NT][2];
#pragma unroll
            for (int i = 0; i < MT; i++)
                ldsm4(af[i][0], af[i][1], af[i][2], af[i][3], sa + (aaddr[i] ^ kx));
#pragma unroll
            for (int jp = 0; jp < NT / 2; jp++)
                ldsm4(bf[2 * jp][0], bf[2 * jp][1], bf[2 * jp + 1][0], bf[2 * jp + 1][1],
                      sb + (baddr[jp] ^ kx));
#pragma unroll
            for (int i = 0; i < MT; i++)
#pragma unroll
                for (int j = 0; j < NT; j++)
                    mma_f16(acc[i][j], af[i], bf[j]);
        }
    }
    __syncthreads();   // all reads done before tile overlays stage smem

    // ---- fused ext-attention epilogue ----
    float* tile = (float*)smc;               // [128][TP]
    float* rsum = tile + 128 * TP;           // [128]
#pragma unroll
    for (int i = 0; i < MT; i++) {
#pragma unroll
        for (int j = 0; j < NT; j++) {
            const int rl = wm * 32 + i * 16 + (lane >> 2);
            const int cl = wn * WNT + j * 8 + (lane & 3) * 2;
            *(float2*)&tile[rl * TP + cl]       = make_float2(acc[i][j][0], acc[i][j][1]);
            *(float2*)&tile[(rl + 8) * TP + cl] = make_float2(acc[i][j][2], acc[i][j][3]);
        }
    }
    __syncthreads();

    for (int p = tid; p < 16 * SEXT; p += 256) {
        const int bl = p >> 6, s = p & 63;
        float* col = &tile[(bl * 8) * TP + s];
        float mx = col[0];
#pragma unroll
        for (int m = 1; m < MODAL; m++) mx = fmaxf(mx, col[m * TP]);
        float sum = 0.f;
        float e[MODAL];
#pragma unroll
        for (int m = 0; m < MODAL; m++) { e[m] = expf(col[m * TP] - mx); sum += e[m]; }
        const float is = 1.f / sum;
#pragma unroll
        for (int m = 0; m < MODAL; m++) col[m * TP] = e[m] * is;
    }
    __syncthreads();

    for (int r = tid; r < 128; r += 256) {
        float t = 0.f;
        const float* row = &tile[r * TP];
#pragma unroll
        for (int s = 0; s < SEXT; s++) t += row[s];
        rsum[r] = 1.f / t;
    }
    __syncthreads();

    for (int idx = tid; idx < 128 * (SEXT / 2); idx += 256) {
        const int r = idx >> 5, sp = (idx & 31) * 2;
        const float rs = rsum[r];
        *(__half2*)&g_ah[(size_t)(bm + r) * SEXT + sp] =
            __floats2half2_rn(tile[r * TP + sp] * rs, tile[r * TP + sp + 1] * rs);
    }
}

// ---------------- attention pass A: scores + global min (fp16 inputs) ----------------
constexpr int QPAD = DMODEL + 4;

extern __shared__ float dynsmem[];

__global__ void __launch_bounds__(256) attn_scores_kernel() {
    float* qs = dynsmem;
    float* ks = dynsmem + MODAL * QPAD;
    const int b = blockIdx.x, tid = threadIdx.x;
    const uint4* qg = (const uint4*)(g_qph + (size_t)b * MODAL * DMODEL);
    const uint4* kg = (const uint4*)(g_kph + (size_t)b * MODAL * DMODEL);
    for (int i = tid; i < MODAL * DMODEL / 8; i += 256) {
        int m = i >> 7, c = i & 127;
        h8_to_f8(qg[i], &qs[m * QPAD + c * 8]);
        h8_to_f8(kg[i], &ks[m * QPAD + c * 8]);
    }
    __syncthreads();

    float lmin = 3.4e38f;
    for (int s = tid; s < NHEAD * MODAL * MODAL; s += 256) {
        int h = s >> 6, m = (s >> 3) & 7, n = s & 7;
        const float4* qr = (const float4*)&qs[m * QPAD + h * DK];
        const float4* kr = (const float4*)&ks[n * QPAD + h * DK];
        float acc = 0.f;
#pragma unroll
        for (int d = 0; d < 16; d++) {
            float4 a = qr[d], c = kr[d];
            acc += a.x * c.x + a.y * c.y + a.z * c.z + a.w * c.w;
        }
        acc *= 0.125f;
        g_scores[(size_t)b * 1024 + s] = acc;
        lmin = fminf(lmin, acc);
    }
#pragma unroll
    for (int o = 16; o; o >>= 1) lmin = fminf(lmin, __shfl_xor_sync(0xffffffffu, lmin, o));
    __shared__ float wmn[8];
    if ((tid & 31) == 0) wmn[tid >> 5] = lmin;
    __syncthreads();
    if (tid == 0) {
        float m = wmn[0];
#pragma unroll
        for (int i = 1; i < 8; i++) m = fminf(m, wmn[i]);
        atomicMin(&g_min_u, enc_min(m));
    }
}

// ---------------- attention pass B (fp16 v input, fp16 output) ----------------
__global__ void __launch_bounds__(256) attn_out_kernel() {
    __shared__ float vs[MODAL * QPAD];
    __shared__ float sc[NHEAD * 64];
    __shared__ float aw[NHEAD * 64];
    const int b = blockIdx.x, tid = threadIdx.x;
    const float inv = 1.f / fabsf(dec_min(g_min_u));

    const uint4* vg = (const uint4*)(g_vph + (size_t)b * MODAL * DMODEL);
    for (int i = tid; i < MODAL * DMODEL / 8; i += 256) {
        int m = i >> 7, c = i & 127;
        h8_to_f8(vg[i], &vs[m * QPAD + c * 8]);
    }
    for (int i = tid; i < 1024; i += 256)
        sc[i] = g_scores[(size_t)b * 1024 + i] * inv;
    __syncthreads();

    if (tid < 128) {
        int h = tid >> 3, m = tid & 7;
        float r[8]; float ss = 0.f;
#pragma unroll
        for (int n = 0; n < 8; n++) { r[n] = sc[h * 64 + m * 8 + n]; ss += r[n] * r[n]; }
        float nrm = fmaxf(sqrtf(ss), 1e-12f);
        float rn = 1.f / nrm;
        float mx = -3.4e38f;
#pragma unroll
        for (int n = 0; n < 8; n++) { r[n] *= rn; mx = fmaxf(mx, r[n]); }
        float sum = 0.f;
#pragma unroll
        for (int n = 0; n < 8; n++) { r[n] = expf(r[n] - mx); sum += r[n]; }
        float is = 1.f / sum;
#pragma unroll
        for (int n = 0; n < 8; n++) aw[h * 64 + m * 8 + n] = r[n] * is;
    }
    __syncthreads();

    __half* og = g_atth + (size_t)b * MODAL * DMODEL;
    for (int o = tid; o < MODAL * DMODEL; o += 256) {
        int m = o >> 10, col = o & 1023, h = col >> 6;
        float acc = 0.f;
#pragma unroll
        for (int n = 0; n < 8; n++) acc += aw[h * 64 + m * 8 + n] * vs[n * QPAD + col];
        og[o] = __float2half_rn(acc);
    }
}

// ---------------- LayerNorm: fp32 x in -> fp32 out + fp16 copy ----------------
__global__ void __launch_bounds__(256) ln_kernel(
    const float* __restrict__ gamma, const float* __restrict__ beta,
    float* __restrict__ out)
{
    const int wid = threadIdx.x >> 5, lane = threadIdx.x & 31;
    const size_t row = (size_t)blockIdx.x * 8 + wid;
    const float4* xr = (const float4*)(g_x + row * DMODEL);
    float4 v[8];
    float s = 0.f, s2 = 0.f;
#pragma unroll
    for (int i = 0; i < 8; i++) {
        v[i] = xr[lane + 32 * i];
        s += v[i].x + v[i].y + v[i].z + v[i].w;
        s2 += v[i].x * v[i].x + v[i].y * v[i].y + v[i].z * v[i].z + v[i].w * v[i].w;
    }
#pragma unroll
    for (int o = 16; o; o >>= 1) {
        s += __shfl_xor_sync(0xffffffffu, s, o);
        s2 += __shfl_xor_sync(0xffffffffu, s2, o);
    }
    const float mu = s * (1.f / DMODEL);
    const float var = fmaxf(s2 * (1.f / DMODEL) - mu * mu, 0.f);
    const float rs = rsqrtf(var + 1e-10f);
    float4* orow = (float4*)(out + row * DMODEL);
    __half2* hrow = (__half2*)(g_xh + row * DMODEL);
    const float4* gm = (const float4*)gamma;
    const float4* bt = (const float4*)beta;
#pragma unroll
    for (int i = 0; i < 8; i++) {
        int c4 = lane + 32 * i;
        float4 g = gm[c4], bb = bt[c4], x = v[i], r;
        r.x = (x.x - mu) * rs * g.x + bb.x;
        r.y = (x.y - mu) * rs * g.y + bb.y;
        r.z = (x.z - mu) * rs * g.z + bb.z;
        r.w = (x.w - mu) * rs * g.w + bb.w;
        orow[c4] = r;
        hrow[2 * c4]     = __float22half2_rn(make_float2(r.x, r.y));
        hrow[2 * c4 + 1] = __float22half2_rn(make_float2(r.z, r.w));
    }
}

// ---------------- launch ----------------
extern "C" void kernel_launch(void* const* d_in, const int* in_sizes, int n_in,
                              void* d_out, int out_size)
{
    const float* q     = (const float*)d_in[0];
    const float* k     = (const float*)d_in[1];
    const float* v     = (const float*)d_in[2];
    const float* Wq    = (const float*)d_in[3];
    const float* Wk    = (const float*)d_in[4];
    const float* Wv    = (const float*)d_in[5];
    const float* Wfc   = (const float*)d_in[6];
    const float* gamma = (const float*)d_in[7];
    const float* beta  = (const float*)d_in[8];
    const float* Wmk   = (const float*)d_in[9];
    const float* Wmv   = (const float*)d_in[10];
    float* out = (float*)d_out;

    float *px;
    __half *pqh, *pkh, *pvh, *pqph, *pkph, *pvph, *patth, *pxh, *pah;
    __half *pwqh, *pwkh, *pwvh, *pwfch, *pwmkh, *pwmvh;
    cudaGetSymbolAddress((void**)&px,    g_x);
    cudaGetSymbolAddress((void**)&pqh,   g_qh);
    cudaGetSymbolAddress((void**)&pkh,   g_kh);
    cudaGetSymbolAddress((void**)&pvh,   g_vh);
    cudaGetSymbolAddress((void**)&pqph,  g_qph);
    cudaGetSymbolAddress((void**)&pkph,  g_kph);
    cudaGetSymbolAddress((void**)&pvph,  g_vph);
    cudaGetSymbolAddress((void**)&patth, g_atth);
    cudaGetSymbolAddress((void**)&pxh,   g_xh);
    cudaGetSymbolAddress((void**)&pah,   g_ah);
    cudaGetSymbolAddress((void**)&pwqh,  g_wqh);
    cudaGetSymbolAddress((void**)&pwkh,  g_wkh);
    cudaGetSymbolAddress((void**)&pwvh,  g_wvh);
    cudaGetSymbolAddress((void**)&pwfch, g_wfch);
    cudaGetSymbolAddress((void**)&pwmkh, g_wmkh);
    cudaGetSymbolAddress((void**)&pwmvh, g_wmvh);

    const int smem_sc = 2 * MODAL * QPAD * (int)sizeof(float);
    cudaFuncSetAttribute(attn_scores_kernel,
                         cudaFuncAttributeMaxDynamicSharedMemorySize, smem_sc);

    const int smem128 = 3 * (128 * 128 + 128 * 128);  // 98304 B
    const int smem64  = 3 * (128 * 128 + 64 * 128);   // 73728 B
    cudaFuncSetAttribute(gemm_proj3,
                         cudaFuncAttributeMaxDynamicSharedMemorySize, smem128);
    cudaFuncSetAttribute(gemm_fc,
                         cudaFuncAttributeMaxDynamicSharedMemorySize, smem128);
    cudaFuncSetAttribute(gemm_final,
                         cudaFuncAttributeMaxDynamicSharedMemorySize, smem128);
    cudaFuncSetAttribute(gemm_xa_ext,
                         cudaFuncAttributeMaxDynamicSharedMemorySize, smem64);

    init_min_kernel<<<1, 1>>>();

    const int a4 = ROWS * DMODEL / 4;
    const int w4 = DMODEL * DMODEL / 4;
    const int s4 = SEXT * DMODEL / 4;

    // fused conversions: activations (3 slots), weights (6 slots)
    cvt_act_kernel<<<dim3((a4 + 255) / 256, 3), 256>>>(
        (const float4*)q, (const float4*)k, (const float4*)v,
        (__half2*)pqh, (__half2*)pkh, (__half2*)pvh, a4);
    cvt_w_kernel<<<dim3((w4 + 255) / 256, 6), 256>>>(
        (const float4*)Wq, (const float4*)Wk, (const float4*)Wv, (const float4*)Wfc,
        (const float4*)Wmk, (const float4*)Wmv,
        (__half2*)pwqh, (__half2*)pwkh, (__half2*)pwvh, (__half2*)pwfch,
        (__half2*)pwmkh, (__half2*)pwmvh, w4, s4);

    // fused q/k/v projections
    gemm_proj3<<<dim3(DMODEL / 128, ROWS / 128, 3), 256, smem128>>>(
        pqh, pkh, pvh, pwqh, pwkh, pwvh, pqph, pkph, pvph);

    attn_scores_kernel<<<BSZ, 256, smem_sc>>>();
    attn_out_kernel<<<BSZ, 256>>>();

    // x = attn_out @ Wfc^T + q (fp32 residual)
    gemm_fc<<<dim3(DMODEL / 128, ROWS / 128), 256, smem128>>>(patth, pwfch, q, px);

    // LayerNorm -> out (fp32) + g_xh (fp16)
    ln_kernel<<<ROWS / 8, 256>>>(gamma, beta, out);

    // fused: xa = x @ Wmk^T + softmax/renorm -> g_ah (fp16)
    gemm_xa_ext<<<dim3(1, ROWS / 128), 256, smem64>>>(pxh, pwmkh);

    // out = x + a @ Wmv^T (K=64)
    gemm_final<<<dim3(DMODEL / 128, ROWS / 128), 256, smem128>>>(pah, pwmvh, out, out);
}

// round 15
// speedup vs baseline: 1.1459x; 1.0031x over previous
#include <cuda_runtime.h>
#include <cuda_fp16.h>
#include <cstdint>

// ---------------- problem constants ----------------
constexpr int MODAL  = 8;
constexpr int DMODEL = 1024;
constexpr int NHEAD  = 16;
constexpr int DK     = 64;
constexpr int SEXT   = 64;
constexpr int BSZ    = 4096;
constexpr int ROWS   = BSZ * MODAL;   // 32768

// ---------------- scratch (device globals) ----------------
__device__ float g_x  [(size_t)ROWS * DMODEL];
// fp16 operands
__device__ __half g_qh  [(size_t)ROWS * DMODEL];
__device__ __half g_kh  [(size_t)ROWS * DMODEL];
__device__ __half g_vh  [(size_t)ROWS * DMODEL];
__device__ __half g_qph [(size_t)ROWS * DMODEL];
__device__ __half g_kph [(size_t)ROWS * DMODEL];
__device__ __half g_vph [(size_t)ROWS * DMODEL];
__device__ __half g_atth[(size_t)ROWS * DMODEL];
__device__ __half g_xh  [(size_t)ROWS * DMODEL];
__device__ __half g_ah  [(size_t)ROWS * SEXT];
__device__ __half g_wqh [(size_t)DMODEL * DMODEL];
__device__ __half g_wkh [(size_t)DMODEL * DMODEL];
__device__ __half g_wvh [(size_t)DMODEL * DMODEL];
__device__ __half g_wfch[(size_t)DMODEL * DMODEL];
__device__ __half g_wmkh[(size_t)SEXT * DMODEL];
__device__ __half g_wmvh[(size_t)DMODEL * SEXT];

// ---------------- helpers ----------------
__device__ __forceinline__ void mma_f16(float* c, const unsigned* a, const unsigned* b) {
    asm volatile(
        "mma.sync.aligned.m16n8k16.row.col.f32.f16.f16.f32 "
        "{%0,%1,%2,%3}, {%4,%5,%6,%7}, {%8,%9}, {%0,%1,%2,%3};\n"
        : "+f"(c[0]), "+f"(c[1]), "+f"(c[2]), "+f"(c[3])
        : "r"(a[0]), "r"(a[1]), "r"(a[2]), "r"(a[3]),
          "r"(b[0]), "r"(b[1]));
}
__device__ __forceinline__ void ldsm4(unsigned& r0, unsigned& r1, unsigned& r2, unsigned& r3,
                                      uint32_t a) {
    asm volatile("ldmatrix.sync.aligned.m8n8.x4.shared.b16 {%0,%1,%2,%3}, [%4];"
                 : "=r"(r0), "=r"(r1), "=r"(r2), "=r"(r3) : "r"(a));
}
__device__ __forceinline__ uint32_t smem_u32(const void* p) {
    uint32_t a;
    asm("{ .reg .u64 t; cvta.to.shared.u64 t, %1; cvt.u32.u64 %0, t; }" : "=r"(a) : "l"(p));
    return a;
}
__device__ __forceinline__ void cp16(uint32_t dst, const void* src) {
    asm volatile("cp.async.cg.shared.global [%0], [%1], 16;" :: "r"(dst), "l"(src));
}
#define CP_COMMIT() asm volatile("cp.async.commit_group;" ::: "memory")
#define CP_WAIT1()  asm volatile("cp.async.wait_group 1;" ::: "memory")

// unpack 8 halves (one uint4) -> 8 floats at dst
__device__ __forceinline__ void h8_to_f8(uint4 u, float* dst) {
    const __half2* hp = (const __half2*)&u;
    float2 f0 = __half22float2(hp[0]);
    float2 f1 = __half22float2(hp[1]);
    float2 f2 = __half22float2(hp[2]);
    float2 f3 = __half22float2(hp[3]);
    *(float4*)dst       = make_float4(f0.x, f0.y, f1.x, f1.y);
    *(float4*)(dst + 4) = make_float4(f2.x, f2.y, f3.x, f3.y);
}

// ---------------- fused fp32->fp16 conversions ----------------
__global__ void __launch_bounds__(256) cvt_act_kernel(
    const float4* __restrict__ s0, const float4* __restrict__ s1, const float4* __restrict__ s2,
    __half2* __restrict__ d0, __half2* __restrict__ d1, __half2* __restrict__ d2, int n4)
{
    const int z = blockIdx.y;
    const float4* s = (z == 0) ? s0 : (z == 1) ? s1 : s2;
    __half2* d = (z == 0) ? d0 : (z == 1) ? d1 : d2;
    int i = blockIdx.x * 256 + threadIdx.x;
    if (i < n4) {
        float4 v = s[i];
        d[2 * i]     = __float22half2_rn(make_float2(v.x, v.y));
        d[2 * i + 1] = __float22half2_rn(make_float2(v.z, v.w));
    }
}

__global__ void __launch_bounds__(256) cvt_w_kernel(
    const float4* __restrict__ s0, const float4* __restrict__ s1,
    const float4* __restrict__ s2, const float4* __restrict__ s3,
    const float4* __restrict__ s4, const float4* __restrict__ s5,
    __half2* __restrict__ d0, __half2* __restrict__ d1,
    __half2* __restrict__ d2, __half2* __restrict__ d3,
    __half2* __restrict__ d4, __half2* __restrict__ d5,
    int nbig, int nsmall)
{
    const int z = blockIdx.y;
    const float4* sa[6] = { s0, s1, s2, s3, s4, s5 };
    __half2* da[6] = { d0, d1, d2, d3, d4, d5 };
    const int n4 = (z < 4) ? nbig : nsmall;
    int i = blockIdx.x * 256 + threadIdx.x;
    if (i < n4) {
        float4 v = sa[z][i];
        da[z][2 * i]     = __float22half2_rn(make_float2(v.x, v.y));
        da[z][2 * i + 1] = __float22half2_rn(make_float2(v.z, v.w));
    }
}

// =====================================================================
// Shared GEMM body: C[M,N] = A[M,K] * B[N,K]^T (+ Res fp32).
// BM=128, BK=64, BN in {128,64}. 256 thr, 8 warps (4Mx2N).
// 3-stage cp.async pipeline, one __syncthreads per k-tile.
// =====================================================================
template<int BN, bool RES, bool OUTH>
__device__ __forceinline__ void gemm_body(
    const __half* __restrict__ A, const __half* __restrict__ B,
    const float* __restrict__ Res, void* __restrict__ Cv, int K, int N,
    char* smc, int bm, int bn)
{
    constexpr int ABYTES = 128 * 128;
    constexpr int BBYTES = BN * 128;
    constexpr int STB    = ABYTES + BBYTES;
    constexpr int BCH    = BN * 8 / 256;
    constexpr int WNT    = BN / 2;
    constexpr int NT     = WNT / 8;
    constexpr int MT     = 2;

    const uint32_t sbase = smem_u32(smc);
    const int tid  = threadIdx.x;
    const int lane = tid & 31;
    const int wid  = tid >> 5;
    const int wm   = wid & 3;
    const int wn   = wid >> 2;

    const int mA = tid >> 3;
    const int cA = tid & 7;
    const int nk = K / 64;

    auto issue = [&](int kt, int s) {
        const uint32_t so = (uint32_t)s * STB;
        const int k0 = kt * 64;
#pragma unroll
        for (int i = 0; i < 4; i++) {
            const int m = mA + 32 * i;
            const uint32_t dst = sbase + so + (uint32_t)m * 128u + (uint32_t)((cA ^ (m & 7)) << 4);
            cp16(dst, A + (size_t)(bm + m) * K + k0 + cA * 8);
        }
#pragma unroll
        for (int i = 0; i < BCH; i++) {
            const int m = mA + 32 * i;
            const uint32_t dst = sbase + so + (uint32_t)ABYTES
                               + (uint32_t)m * 128u + (uint32_t)((cA ^ (m & 7)) << 4);
            cp16(dst, B + (size_t)(bn + m) * K + k0 + cA * 8);
        }
    };

    float acc[MT][NT][4];
#pragma unroll
    for (int i = 0; i < MT; i++)
#pragma unroll
        for (int j = 0; j < NT; j++)
#pragma unroll
            for (int t = 0; t < 4; t++) acc[i][j][t] = 0.f;

    issue(0, 0); CP_COMMIT();
    if (nk > 1) issue(1, 1);
    CP_COMMIT();

    uint32_t aaddr[MT];
    {
        const int g = lane >> 3;
        const int arow_in = (g & 1) * 8 + (lane & 7);
        const uint32_t apar = (uint32_t)(g >> 1);
#pragma unroll
        for (int i = 0; i < MT; i++) {
            const int row = wm * 32 + i * 16 + arow_in;
            aaddr[i] = (uint32_t)row * 128u + ((((uint32_t)row & 7u) ^ apar) << 4);
        }
    }
    uint32_t baddr[NT / 2];
    {
        const int g = lane >> 3;
        const int nrow_in = ((g >> 1) & 1) * 8 + (lane & 7);
        const uint32_t bpar = (uint32_t)(g & 1);
#pragma unroll
        for (int jp = 0; jp < NT / 2; jp++) {
            const int n = wn * WNT + jp * 16 + nrow_in;
            baddr[jp] = (uint32_t)n * 128u + ((((uint32_t)n & 7u) ^ bpar) << 4);
        }
    }

    for (int kt = 0; kt < nk; kt++) {
        CP_WAIT1();
        __syncthreads();
        if (kt + 2 < nk) issue(kt + 2, (kt + 2) % 3);
        CP_COMMIT();

        const uint32_t sa = sbase + (uint32_t)(kt % 3) * STB;
        const uint32_t sb = sa + ABYTES;

#pragma unroll
        for (int ks = 0; ks < 4; ks++) {
            const uint32_t kx = (uint32_t)(2 * ks) << 4;
            unsigned af[MT][4], bf[NT][2];
#pragma unroll
            for (int i = 0; i < MT; i++)
                ldsm4(af[i][0], af[i][1], af[i][2], af[i][3], sa + (aaddr[i] ^ kx));
#pragma unroll
            for (int jp = 0; jp < NT / 2; jp++)
                ldsm4(bf[2 * jp][0], bf[2 * jp][1], bf[2 * jp + 1][0], bf[2 * jp + 1][1],
                      sb + (baddr[jp] ^ kx));
#pragma unroll
            for (int i = 0; i < MT; i++)
#pragma unroll
                for (int j = 0; j < NT; j++)
                    mma_f16(acc[i][j], af[i], bf[j]);
        }
    }

#pragma unroll
    for (int i = 0; i < MT; i++) {
#pragma unroll
        for (int j = 0; j < NT; j++) {
            const int r0 = bm + wm * 32 + i * 16 + (lane >> 2);
            const int c0 = bn + wn * WNT + j * 8 + (lane & 3) * 2;
            float2 v0 = make_float2(acc[i][j][0], acc[i][j][1]);
            float2 v1 = make_float2(acc[i][j][2], acc[i][j][3]);
            if (OUTH) {
                __half* Co = (__half*)Cv;
                *(__half2*)&Co[(size_t)r0 * N + c0]       = __floats2half2_rn(v0.x, v0.y);
                *(__half2*)&Co[(size_t)(r0 + 8) * N + c0] = __floats2half2_rn(v1.x, v1.y);
            } else {
                float* Cf = (float*)Cv;
                if (RES) {
                    float2 ra = *(const float2*)&Res[(size_t)r0 * N + c0];
                    float2 rb = *(const float2*)&Res[(size_t)(r0 + 8) * N + c0];
                    v0.x += ra.x; v0.y += ra.y;
                    v1.x += rb.x; v1.y += rb.y;
                }
                *(float2*)&Cf[(size_t)r0 * N + c0] = v0;
                *(float2*)&Cf[(size_t)(r0 + 8) * N + c0] = v1;
            }
        }
    }
}

// ---- fused 3-way projection GEMM (grid.z selects q/k/v) ----
__global__ void __launch_bounds__(256, 2) gemm_proj3(
    const __half* A0, const __half* A1, const __half* A2,
    const __half* B0, const __half* B1, const __half* B2,
    __half* C0, __half* C1, __half* C2)
{
    extern __shared__ char smc[];
    const int z = blockIdx.z;
    const __half* A = (z == 0) ? A0 : (z == 1) ? A1 : A2;
    const __half* B = (z == 0) ? B0 : (z == 1) ? B1 : B2;
    __half* C = (z == 0) ? C0 : (z == 1) ? C1 : C2;
    gemm_body<128, false, true>(A, B, nullptr, C, DMODEL, DMODEL,
                                smc, blockIdx.y * 128, blockIdx.x * 128);
}

// ---- FC GEMM: x = attn_out @ Wfc^T + q (fp32 out) ----
__global__ void __launch_bounds__(256, 2) gemm_fc(
    const __half* __restrict__ A, const __half* __restrict__ B,
    const float* __restrict__ Res, float* __restrict__ C)
{
    extern __shared__ char smc[];
    gemm_body<128, true, false>(A, B, Res, C, DMODEL, DMODEL,
                                smc, blockIdx.y * 128, blockIdx.x * 128);
}

// ---- final GEMM: out = x + a @ Wmv^T (K=64) ----
__global__ void __launch_bounds__(256, 2) gemm_final(
    const __half* __restrict__ A, const __half* __restrict__ B,
    const float* __restrict__ Res, float* __restrict__ C)
{
    extern __shared__ char smc[];
    gemm_body<128, true, false>(A, B, Res, C, SEXT, DMODEL,
                                smc, blockIdx.y * 128, blockIdx.x * 128);
}

// =====================================================================
// Fused xa GEMM + ExternalAttention normalization.
// =====================================================================
__global__ void __launch_bounds__(256, 2) gemm_xa_ext(
    const __half* __restrict__ A, const __half* __restrict__ B)
{
    constexpr int BN     = 64;
    constexpr int ABYTES = 128 * 128;
    constexpr int BBYTES = BN * 128;
    constexpr int STB    = ABYTES + BBYTES;
    constexpr int BCH    = 2;
    constexpr int WNT    = 32;
    constexpr int NT     = 4;
    constexpr int MT     = 2;
    constexpr int K      = DMODEL;
    constexpr int TP     = 66;

    extern __shared__ char smc[];
    const uint32_t sbase = smem_u32(smc);

    const int tid  = threadIdx.x;
    const int lane = tid & 31;
    const int wid  = tid >> 5;
    const int wm   = wid & 3;
    const int wn   = wid >> 2;
    const int bm   = blockIdx.y * 128;

    const int mA = tid >> 3;
    const int cA = tid & 7;
    constexpr int nk = K / 64;

    auto issue = [&](int kt, int s) {
        const uint32_t so = (uint32_t)s * STB;
        const int k0 = kt * 64;
#pragma unroll
        for (int i = 0; i < 4; i++) {
            const int m = mA + 32 * i;
            const uint32_t dst = sbase + so + (uint32_t)m * 128u + (uint32_t)((cA ^ (m & 7)) << 4);
            cp16(dst, A + (size_t)(bm + m) * K + k0 + cA * 8);
        }
#pragma unroll
        for (int i = 0; i < BCH; i++) {
            const int m = mA + 32 * i;
            const uint32_t dst = sbase + so + (uint32_t)ABYTES
                               + (uint32_t)m * 128u + (uint32_t)((cA ^ (m & 7)) << 4);
            cp16(dst, B + (size_t)m * K + k0 + cA * 8);
        }
    };

    float acc[MT][NT][4];
#pragma unroll
    for (int i = 0; i < MT; i++)
#pragma unroll
        for (int j = 0; j < NT; j++)
#pragma unroll
            for (int t = 0; t < 4; t++) acc[i][j][t] = 0.f;

    issue(0, 0); CP_COMMIT();
    issue(1, 1); CP_COMMIT();

    uint32_t aaddr[MT];
    {
        const int g = lane >> 3;
        const int arow_in = (g & 1) * 8 + (lane & 7);
        const uint32_t apar = (uint32_t)(g >> 1);
#pragma unroll
        for (int i = 0; i < MT; i++) {
            const int row = wm * 32 + i * 16 + arow_in;
            aaddr[i] = (uint32_t)row * 128u + ((((uint32_t)row & 7u) ^ apar) << 4);
        }
    }
    uint32_t baddr[NT / 2];
    {
        const int g = lane >> 3;
        const int nrow_in = ((g >> 1) & 1) * 8 + (lane & 7);
        const uint32_t bpar = (uint32_t)(g & 1);
#pragma unroll
        for (int jp = 0; jp < NT / 2; jp++) {
            const int n = wn * WNT + jp * 16 + nrow_in;
            baddr[jp] = (uint32_t)n * 128u + ((((uint32_t)n & 7u) ^ bpar) << 4);
        }
    }

    for (int kt = 0; kt < nk; kt++) {
        CP_WAIT1();
        __syncthreads();
        if (kt + 2 < nk) issue(kt + 2, (kt + 2) % 3);
        CP_COMMIT();

        const uint32_t sa = sbase + (uint32_t)(kt % 3) * STB;
        const uint32_t sb = sa + ABYTES;

#pragma unroll
        for (int ks = 0; ks < 4; ks++) {
            const uint32_t kx = (uint32_t)(2 * ks) << 4;
            unsigned af[MT][4], bf[NT][2];
#pragma unroll
            for (int i = 0; i < MT; i++)
                ldsm4(af[i][0], af[i][1], af[i][2], af[i][3], sa + (aaddr[i] ^ kx));
#pragma unroll
            for (int jp = 0; jp < NT / 2; jp++)
                ldsm4(bf[2 * jp][0], bf[2 * jp][1], bf[2 * jp + 1][0], bf[2 * jp + 1][1],
                      sb + (baddr[jp] ^ kx));
#pragma unroll
            for (int i = 0; i < MT; i++)
#pragma unroll
                for (int j = 0; j < NT; j++)
                    mma_f16(acc[i][j], af[i], bf[j]);
        }
    }
    __syncthreads();

    // ---- fused ext-attention epilogue ----
    float* tile = (float*)smc;
    float* rsum = tile + 128 * TP;
#pragma unroll
    for (int i = 0; i < MT; i++) {
#pragma unroll
        for (int j = 0; j < NT; j++) {
            const int rl = wm * 32 + i * 16 + (lane >> 2);
            const int cl = wn * WNT + j * 8 + (lane & 3) * 2;
            *(float2*)&tile[rl * TP + cl]       = make_float2(acc[i][j][0], acc[i][j][1]);
            *(float2*)&tile[(rl + 8) * TP + cl] = make_float2(acc[i][j][2], acc[i][j][3]);
        }
    }
    __syncthreads();

    for (int p = tid; p < 16 * SEXT; p += 256) {
        const int bl = p >> 6, s = p & 63;
        float* col = &tile[(bl * 8) * TP + s];
        float mx = col[0];
#pragma unroll
        for (int m = 1; m < MODAL; m++) mx = fmaxf(mx, col[m * TP]);
        float sum = 0.f;
        float e[MODAL];
#pragma unroll
        for (int m = 0; m < MODAL; m++) { e[m] = expf(col[m * TP] - mx); sum += e[m]; }
        const float is = 1.f / sum;
#pragma unroll
        for (int m = 0; m < MODAL; m++) col[m * TP] = e[m] * is;
    }
    __syncthreads();

    for (int r = tid; r < 128; r += 256) {
        float t = 0.f;
        const float* row = &tile[r * TP];
#pragma unroll
        for (int s = 0; s < SEXT; s++) t += row[s];
        rsum[r] = 1.f / t;
    }
    __syncthreads();

    for (int idx = tid; idx < 128 * (SEXT / 2); idx += 256) {
        const int r = idx >> 5, sp = (idx & 31) * 2;
        const float rs = rsum[r];
        *(__half2*)&g_ah[(size_t)(bm + r) * SEXT + sp] =
            __floats2half2_rn(tile[r * TP + sp] * rs, tile[r * TP + sp + 1] * rs);
    }
}

// =====================================================================
// FUSED attention: one kernel per batch.
// Identity used: (s/|min s|) / max(||s/|min s|||, 1e-12) == s / ||s||
// (global-min scaling cancels in the L2 normalization; eps never binds).
// Loads q,k,v fp16 -> f32 smem, scores, L2-norm softmax, attn @ V -> fp16.
// =====================================================================
constexpr int QPAD = DMODEL + 4;
// smem floats: qs/ks/vs [8*QPAD each] + sc[1024] + aw[1024]
constexpr int ATTN_SMEM = (3 * MODAL * QPAD + 2048) * (int)sizeof(float);

extern __shared__ float dynsmem[];

__global__ void __launch_bounds__(256) attn_fused_kernel() {
    float* qs = dynsmem;
    float* ks = qs + MODAL * QPAD;
    float* vs = ks + MODAL * QPAD;
    float* sc = vs + MODAL * QPAD;    // [16*64] raw scores
    float* aw = sc + 1024;            // [16*64] attention weights
    const int b = blockIdx.x, tid = threadIdx.x;

    const uint4* qg = (const uint4*)(g_qph + (size_t)b * MODAL * DMODEL);
    const uint4* kg = (const uint4*)(g_kph + (size_t)b * MODAL * DMODEL);
    const uint4* vg = (const uint4*)(g_vph + (size_t)b * MODAL * DMODEL);
    for (int i = tid; i < MODAL * DMODEL / 8; i += 256) {
        int m = i >> 7, c = i & 127;
        h8_to_f8(qg[i], &qs[m * QPAD + c * 8]);
        h8_to_f8(kg[i], &ks[m * QPAD + c * 8]);
        h8_to_f8(vg[i], &vs[m * QPAD + c * 8]);
    }
    __syncthreads();

    // scores: s[h][m][n] = (q_h[m] . k_h[n]) / 8
    for (int s = tid; s < NHEAD * MODAL * MODAL; s += 256) {
        int h = s >> 6, m = (s >> 3) & 7, n = s & 7;
        const float4* qr = (const float4*)&qs[m * QPAD + h * DK];
        const float4* kr = (const float4*)&ks[n * QPAD + h * DK];
        float acc = 0.f;
#pragma unroll
        for (int d = 0; d < 16; d++) {
            float4 a = qr[d], c = kr[d];
            acc += a.x * c.x + a.y * c.y + a.z * c.z + a.w * c.w;
        }
        sc[s] = acc * 0.125f;
    }
    __syncthreads();

    // per-(h,m) row: softmax(s / ||s||)
    if (tid < 128) {
        int h = tid >> 3, m = tid & 7;
        float r[8]; float ss = 0.f;
#pragma unroll
        for (int n = 0; n < 8; n++) { r[n] = sc[h * 64 + m * 8 + n]; ss += r[n] * r[n]; }
        const float rn = 1.f / fmaxf(sqrtf(ss), 1e-30f);
        float mx = -3.4e38f;
#pragma unroll
        for (int n = 0; n < 8; n++) { r[n] *= rn; mx = fmaxf(mx, r[n]); }
        float sum = 0.f;
#pragma unroll
        for (int n = 0; n < 8; n++) { r[n] = expf(r[n] - mx); sum += r[n]; }
        const float is = 1.f / sum;
#pragma unroll
        for (int n = 0; n < 8; n++) aw[h * 64 + m * 8 + n] = r[n] * is;
    }
    __syncthreads();

    // out = attn @ V -> fp16
    __half* og = g_atth + (size_t)b * MODAL * DMODEL;
    for (int o = tid; o < MODAL * DMODEL; o += 256) {
        int m = o >> 10, col = o & 1023, h = col >> 6;
        float acc = 0.f;
#pragma unroll
        for (int n = 0; n < 8; n++) acc += aw[h * 64 + m * 8 + n] * vs[n * QPAD + col];
        og[o] = __float2half_rn(acc);
    }
}

// ---------------- LayerNorm: fp32 x in -> fp32 out + fp16 copy ----------------
__global__ void __launch_bounds__(256) ln_kernel(
    const float* __restrict__ gamma, const float* __restrict__ beta,
    float* __restrict__ out)
{
    const int wid = threadIdx.x >> 5, lane = threadIdx.x & 31;
    const size_t row = (size_t)blockIdx.x * 8 + wid;
    const float4* xr = (const float4*)(g_x + row * DMODEL);
    float4 v[8];
    float s = 0.f, s2 = 0.f;
#pragma unroll
    for (int i = 0; i < 8; i++) {
        v[i] = xr[lane + 32 * i];
        s += v[i].x + v[i].y + v[i].z + v[i].w;
        s2 += v[i].x * v[i].x + v[i].y * v[i].y + v[i].z * v[i].z + v[i].w * v[i].w;
    }
#pragma unroll
    for (int o = 16; o; o >>= 1) {
        s += __shfl_xor_sync(0xffffffffu, s, o);
        s2 += __shfl_xor_sync(0xffffffffu, s2, o);
    }
    const float mu = s * (1.f / DMODEL);
    const float var = fmaxf(s2 * (1.f / DMODEL) - mu * mu, 0.f);
    const float rs = rsqrtf(var + 1e-10f);
    float4* orow = (float4*)(out + row * DMODEL);
    __half2* hrow = (__half2*)(g_xh + row * DMODEL);
    const float4* gm = (const float4*)gamma;
    const float4* bt = (const float4*)beta;
#pragma unroll
    for (int i = 0; i < 8; i++) {
        int c4 = lane + 32 * i;
        float4 g = gm[c4], bb = bt[c4], x = v[i], r;
        r.x = (x.x - mu) * rs * g.x + bb.x;
        r.y = (x.y - mu) * rs * g.y + bb.y;
        r.z = (x.z - mu) * rs * g.z + bb.z;
        r.w = (x.w - mu) * rs * g.w + bb.w;
        orow[c4] = r;
        hrow[2 * c4]     = __float22half2_rn(make_float2(r.x, r.y));
        hrow[2 * c4 + 1] = __float22half2_rn(make_float2(r.z, r.w));
    }
}

// ---------------- launch ----------------
extern "C" void kernel_launch(void* const* d_in, const int* in_sizes, int n_in,
                              void* d_out, int out_size)
{
    const float* q     = (const float*)d_in[0];
    const float* k     = (const float*)d_in[1];
    const float* v     = (const float*)d_in[2];
    const float* Wq    = (const float*)d_in[3];
    const float* Wk    = (const float*)d_in[4];
    const float* Wv    = (const float*)d_in[5];
    const float* Wfc   = (const float*)d_in[6];
    const float* gamma = (const float*)d_in[7];
    const float* beta  = (const float*)d_in[8];
    const float* Wmk   = (const float*)d_in[9];
    const float* Wmv   = (const float*)d_in[10];
    float* out = (float*)d_out;

    float *px;
    __half *pqh, *pkh, *pvh, *pqph, *pkph, *pvph, *patth, *pxh, *pah;
    __half *pwqh, *pwkh, *pwvh, *pwfch, *pwmkh, *pwmvh;
    cudaGetSymbolAddress((void**)&px,    g_x);
    cudaGetSymbolAddress((void**)&pqh,   g_qh);
    cudaGetSymbolAddress((void**)&pkh,   g_kh);
    cudaGetSymbolAddress((void**)&pvh,   g_vh);
    cudaGetSymbolAddress((void**)&pqph,  g_qph);
    cudaGetSymbolAddress((void**)&pkph,  g_kph);
    cudaGetSymbolAddress((void**)&pvph,  g_vph);
    cudaGetSymbolAddress((void**)&patth, g_atth);
    cudaGetSymbolAddress((void**)&pxh,   g_xh);
    cudaGetSymbolAddress((void**)&pah,   g_ah);
    cudaGetSymbolAddress((void**)&pwqh,  g_wqh);
    cudaGetSymbolAddress((void**)&pwkh,  g_wkh);
    cudaGetSymbolAddress((void**)&pwvh,  g_wvh);
    cudaGetSymbolAddress((void**)&pwfch, g_wfch);
    cudaGetSymbolAddress((void**)&pwmkh, g_wmkh);
    cudaGetSymbolAddress((void**)&pwmvh, g_wmvh);

    cudaFuncSetAttribute(attn_fused_kernel,
                         cudaFuncAttributeMaxDynamicSharedMemorySize, ATTN_SMEM);

    const int smem128 = 3 * (128 * 128 + 128 * 128);  // 98304 B
    const int smem64  = 3 * (128 * 128 + 64 * 128);   // 73728 B
    cudaFuncSetAttribute(gemm_proj3,
                         cudaFuncAttributeMaxDynamicSharedMemorySize, smem128);
    cudaFuncSetAttribute(gemm_fc,
                         cudaFuncAttributeMaxDynamicSharedMemorySize, smem128);
    cudaFuncSetAttribute(gemm_final,
                         cudaFuncAttributeMaxDynamicSharedMemorySize, smem128);
    cudaFuncSetAttribute(gemm_xa_ext,
                         cudaFuncAttributeMaxDynamicSharedMemorySize, smem64);

    const int a4 = ROWS * DMODEL / 4;
    const int w4 = DMODEL * DMODEL / 4;
    const int s4 = SEXT * DMODEL / 4;

    // fused conversions: activations (3 slots), weights (6 slots)
    cvt_act_kernel<<<dim3((a4 + 255) / 256, 3), 256>>>(
        (const float4*)q, (const float4*)k, (const float4*)v,
        (__half2*)pqh, (__half2*)pkh, (__half2*)pvh, a4);
    cvt_w_kernel<<<dim3((w4 + 255) / 256, 6), 256>>>(
        (const float4*)Wq, (const float4*)Wk, (const float4*)Wv, (const float4*)Wfc,
        (const float4*)Wmk, (const float4*)Wmv,
        (__half2*)pwqh, (__half2*)pwkh, (__half2*)pwvh, (__half2*)pwfch,
        (__half2*)pwmkh, (__half2*)pwmvh, w4, s4);

    // fused q/k/v projections
    gemm_proj3<<<dim3(DMODEL / 128, ROWS / 128, 3), 256, smem128>>>(
        pqh, pkh, pvh, pwqh, pwkh, pwvh, pqph, pkph, pvph);

    // fused attention (global-min algebraically eliminated)
    attn_fused_kernel<<<BSZ, 256, ATTN_SMEM>>>();

    // x = attn_out @ Wfc^T + q (fp32 residual)
    gemm_fc<<<dim3(DMODEL / 128, ROWS / 128), 256, smem128>>>(patth, pwfch, q, px);

    // LayerNorm -> out (fp32) + g_xh (fp16)
    ln_kernel<<<ROWS / 8, 256>>>(gamma, beta, out);

    // fused: xa = x @ Wmk^T + softmax/renorm -> g_ah (fp16)
    gemm_xa_ext<<<dim3(1, ROWS / 128), 256, smem64>>>(pxh, pwmkh);

    // out = x + a @ Wmv^T (K=64)
    gemm_final<<<dim3(DMODEL / 128, ROWS / 128), 256, smem128>>>(pah, pwmvh, out, out);
}

// round 16
// speedup vs baseline: 1.2019x; 1.0489x over previous
#include <cuda_runtime.h>
#include <cuda_fp16.h>
#include <cstdint>

// ---------------- problem constants ----------------
constexpr int MODAL  = 8;
constexpr int DMODEL = 1024;
constexpr int NHEAD  = 16;
constexpr int DK     = 64;
constexpr int SEXT   = 64;
constexpr int BSZ    = 4096;
constexpr int ROWS   = BSZ * MODAL;   // 32768

// ---------------- scratch (device globals) ----------------
__device__ float g_x  [(size_t)ROWS * DMODEL];
// fp16 operands
__device__ __half g_qh  [(size_t)ROWS * DMODEL];
__device__ __half g_kh  [(size_t)ROWS * DMODEL];
__device__ __half g_vh  [(size_t)ROWS * DMODEL];
__device__ __half g_qph [(size_t)ROWS * DMODEL];
__device__ __half g_kph [(size_t)ROWS * DMODEL];
__device__ __half g_vph [(size_t)ROWS * DMODEL];
__device__ __half g_atth[(size_t)ROWS * DMODEL];
__device__ __half g_xh  [(size_t)ROWS * DMODEL];
__device__ __half g_ah  [(size_t)ROWS * SEXT];
__device__ __half g_wqh [(size_t)DMODEL * DMODEL];
__device__ __half g_wkh [(size_t)DMODEL * DMODEL];
__device__ __half g_wvh [(size_t)DMODEL * DMODEL];
__device__ __half g_wfch[(size_t)DMODEL * DMODEL];
__device__ __half g_wmkh[(size_t)SEXT * DMODEL];
__device__ __half g_wmvh[(size_t)DMODEL * SEXT];

// ---------------- helpers ----------------
__device__ __forceinline__ void mma_f16(float* c, const unsigned* a, const unsigned* b) {
    asm volatile(
        "mma.sync.aligned.m16n8k16.row.col.f32.f16.f16.f32 "
        "{%0,%1,%2,%3}, {%4,%5,%6,%7}, {%8,%9}, {%0,%1,%2,%3};\n"
        : "+f"(c[0]), "+f"(c[1]), "+f"(c[2]), "+f"(c[3])
        : "r"(a[0]), "r"(a[1]), "r"(a[2]), "r"(a[3]),
          "r"(b[0]), "r"(b[1]));
}
__device__ __forceinline__ void ldsm4(unsigned& r0, unsigned& r1, unsigned& r2, unsigned& r3,
                                      uint32_t a) {
    asm volatile("ldmatrix.sync.aligned.m8n8.x4.shared.b16 {%0,%1,%2,%3}, [%4];"
                 : "=r"(r0), "=r"(r1), "=r"(r2), "=r"(r3) : "r"(a));
}
__device__ __forceinline__ uint32_t smem_u32(const void* p) {
    uint32_t a;
    asm("{ .reg .u64 t; cvta.to.shared.u64 t, %1; cvt.u32.u64 %0, t; }" : "=r"(a) : "l"(p));
    return a;
}
__device__ __forceinline__ void cp16(uint32_t dst, const void* src) {
    asm volatile("cp.async.cg.shared.global [%0], [%1], 16;" :: "r"(dst), "l"(src));
}
#define CP_COMMIT() asm volatile("cp.async.commit_group;" ::: "memory")
#define CP_WAIT1()  asm volatile("cp.async.wait_group 1;" ::: "memory")

// unpack 8 halves (one uint4) -> 8 floats at dst
__device__ __forceinline__ void h8_to_f8(uint4 u, float* dst) {
    const __half2* hp = (const __half2*)&u;
    float2 f0 = __half22float2(hp[0]);
    float2 f1 = __half22float2(hp[1]);
    float2 f2 = __half22float2(hp[2]);
    float2 f3 = __half22float2(hp[3]);
    dst[0] = f0.x; dst[1] = f0.y; dst[2] = f1.x; dst[3] = f1.y;
    dst[4] = f2.x; dst[5] = f2.y; dst[6] = f3.x; dst[7] = f3.y;
}

// ---------------- fused fp32->fp16 conversions ----------------
__global__ void __launch_bounds__(256) cvt_act_kernel(
    const float4* __restrict__ s0, const float4* __restrict__ s1, const float4* __restrict__ s2,
    __half2* __restrict__ d0, __half2* __restrict__ d1, __half2* __restrict__ d2, int n4)
{
    const int z = blockIdx.y;
    const float4* s = (z == 0) ? s0 : (z == 1) ? s1 : s2;
    __half2* d = (z == 0) ? d0 : (z == 1) ? d1 : d2;
    int i = blockIdx.x * 256 + threadIdx.x;
    if (i < n4) {
        float4 v = s[i];
        d[2 * i]     = __float22half2_rn(make_float2(v.x, v.y));
        d[2 * i + 1] = __float22half2_rn(make_float2(v.z, v.w));
    }
}

__global__ void __launch_bounds__(256) cvt_w_kernel(
    const float4* __restrict__ s0, const float4* __restrict__ s1,
    const float4* __restrict__ s2, const float4* __restrict__ s3,
    const float4* __restrict__ s4, const float4* __restrict__ s5,
    __half2* __restrict__ d0, __half2* __restrict__ d1,
    __half2* __restrict__ d2, __half2* __restrict__ d3,
    __half2* __restrict__ d4, __half2* __restrict__ d5,
    int nbig, int nsmall)
{
    const int z = blockIdx.y;
    const float4* sa[6] = { s0, s1, s2, s3, s4, s5 };
    __half2* da[6] = { d0, d1, d2, d3, d4, d5 };
    const int n4 = (z < 4) ? nbig : nsmall;
    int i = blockIdx.x * 256 + threadIdx.x;
    if (i < n4) {
        float4 v = sa[z][i];
        da[z][2 * i]     = __float22half2_rn(make_float2(v.x, v.y));
        da[z][2 * i + 1] = __float22half2_rn(make_float2(v.z, v.w));
    }
}

// =====================================================================
// Shared GEMM body: C[M,N] = A[M,K] * B[N,K]^T (+ Res fp32).
// BM=128, BK=64, BN in {128,64}. 256 thr, 8 warps (4Mx2N).
// 3-stage cp.async pipeline, one __syncthreads per k-tile.
// =====================================================================
template<int BN, bool RES, bool OUTH>
__device__ __forceinline__ void gemm_body(
    const __half* __restrict__ A, const __half* __restrict__ B,
    const float* __restrict__ Res, void* __restrict__ Cv, int K, int N,
    char* smc, int bm, int bn)
{
    constexpr int ABYTES = 128 * 128;
    constexpr int BBYTES = BN * 128;
    constexpr int STB    = ABYTES + BBYTES;
    constexpr int BCH    = BN * 8 / 256;
    constexpr int WNT    = BN / 2;
    constexpr int NT     = WNT / 8;
    constexpr int MT     = 2;

    const uint32_t sbase = smem_u32(smc);
    const int tid  = threadIdx.x;
    const int lane = tid & 31;
    const int wid  = tid >> 5;
    const int wm   = wid & 3;
    const int wn   = wid >> 2;

    const int mA = tid >> 3;
    const int cA = tid & 7;
    const int nk = K / 64;

    auto issue = [&](int kt, int s) {
        const uint32_t so = (uint32_t)s * STB;
        const int k0 = kt * 64;
#pragma unroll
        for (int i = 0; i < 4; i++) {
            const int m = mA + 32 * i;
            const uint32_t dst = sbase + so + (uint32_t)m * 128u + (uint32_t)((cA ^ (m & 7)) << 4);
            cp16(dst, A + (size_t)(bm + m) * K + k0 + cA * 8);
        }
#pragma unroll
        for (int i = 0; i < BCH; i++) {
            const int m = mA + 32 * i;
            const uint32_t dst = sbase + so + (uint32_t)ABYTES
                               + (uint32_t)m * 128u + (uint32_t)((cA ^ (m & 7)) << 4);
            cp16(dst, B + (size_t)(bn + m) * K + k0 + cA * 8);
        }
    };

    float acc[MT][NT][4];
#pragma unroll
    for (int i = 0; i < MT; i++)
#pragma unroll
        for (int j = 0; j < NT; j++)
#pragma unroll
            for (int t = 0; t < 4; t++) acc[i][j][t] = 0.f;

    issue(0, 0); CP_COMMIT();
    if (nk > 1) issue(1, 1);
    CP_COMMIT();

    uint32_t aaddr[MT];
    {
        const int g = lane >> 3;
        const int arow_in = (g & 1) * 8 + (lane & 7);
        const uint32_t apar = (uint32_t)(g >> 1);
#pragma unroll
        for (int i = 0; i < MT; i++) {
            const int row = wm * 32 + i * 16 + arow_in;
            aaddr[i] = (uint32_t)row * 128u + ((((uint32_t)row & 7u) ^ apar) << 4);
        }
    }
    uint32_t baddr[NT / 2];
    {
        const int g = lane >> 3;
        const int nrow_in = ((g >> 1) & 1) * 8 + (lane & 7);
        const uint32_t bpar = (uint32_t)(g & 1);
#pragma unroll
        for (int jp = 0; jp < NT / 2; jp++) {
            const int n = wn * WNT + jp * 16 + nrow_in;
            baddr[jp] = (uint32_t)n * 128u + ((((uint32_t)n & 7u) ^ bpar) << 4);
        }
    }

    for (int kt = 0; kt < nk; kt++) {
        CP_WAIT1();
        __syncthreads();
        if (kt + 2 < nk) issue(kt + 2, (kt + 2) % 3);
        CP_COMMIT();

        const uint32_t sa = sbase + (uint32_t)(kt % 3) * STB;
        const uint32_t sb = sa + ABYTES;

#pragma unroll
        for (int ks = 0; ks < 4; ks++) {
            const uint32_t kx = (uint32_t)(2 * ks) << 4;
            unsigned af[MT][4], bf[NT][2];
#pragma unroll
            for (int i = 0; i < MT; i++)
                ldsm4(af[i][0], af[i][1], af[i][2], af[i][3], sa + (aaddr[i] ^ kx));
#pragma unroll
            for (int jp = 0; jp < NT / 2; jp++)
                ldsm4(bf[2 * jp][0], bf[2 * jp][1], bf[2 * jp + 1][0], bf[2 * jp + 1][1],
                      sb + (baddr[jp] ^ kx));
#pragma unroll
            for (int i = 0; i < MT; i++)
#pragma unroll
                for (int j = 0; j < NT; j++)
                    mma_f16(acc[i][j], af[i], bf[j]);
        }
    }

#pragma unroll
    for (int i = 0; i < MT; i++) {
#pragma unroll
        for (int j = 0; j < NT; j++) {
            const int r0 = bm + wm * 32 + i * 16 + (lane >> 2);
            const int c0 = bn + wn * WNT + j * 8 + (lane & 3) * 2;
            float2 v0 = make_float2(acc[i][j][0], acc[i][j][1]);
            float2 v1 = make_float2(acc[i][j][2], acc[i][j][3]);
            if (OUTH) {
                __half* Co = (__half*)Cv;
                *(__half2*)&Co[(size_t)r0 * N + c0]       = __floats2half2_rn(v0.x, v0.y);
                *(__half2*)&Co[(size_t)(r0 + 8) * N + c0] = __floats2half2_rn(v1.x, v1.y);
            } else {
                float* Cf = (float*)Cv;
                if (RES) {
                    float2 ra = *(const float2*)&Res[(size_t)r0 * N + c0];
                    float2 rb = *(const float2*)&Res[(size_t)(r0 + 8) * N + c0];
                    v0.x += ra.x; v0.y += ra.y;
                    v1.x += rb.x; v1.y += rb.y;
                }
                *(float2*)&Cf[(size_t)r0 * N + c0] = v0;
                *(float2*)&Cf[(size_t)(r0 + 8) * N + c0] = v1;
            }
        }
    }
}

// ---- fused 3-way projection GEMM (grid.z selects q/k/v) ----
__global__ void __launch_bounds__(256, 2) gemm_proj3(
    const __half* A0, const __half* A1, const __half* A2,
    const __half* B0, const __half* B1, const __half* B2,
    __half* C0, __half* C1, __half* C2)
{
    extern __shared__ char smc[];
    const int z = blockIdx.z;
    const __half* A = (z == 0) ? A0 : (z == 1) ? A1 : A2;
    const __half* B = (z == 0) ? B0 : (z == 1) ? B1 : B2;
    __half* C = (z == 0) ? C0 : (z == 1) ? C1 : C2;
    gemm_body<128, false, true>(A, B, nullptr, C, DMODEL, DMODEL,
                                smc, blockIdx.y * 128, blockIdx.x * 128);
}

// ---- FC GEMM: x = attn_out @ Wfc^T + q (fp32 out) ----
__global__ void __launch_bounds__(256, 2) gemm_fc(
    const __half* __restrict__ A, const __half* __restrict__ B,
    const float* __restrict__ Res, float* __restrict__ C)
{
    extern __shared__ char smc[];
    gemm_body<128, true, false>(A, B, Res, C, DMODEL, DMODEL,
                                smc, blockIdx.y * 128, blockIdx.x * 128);
}

// ---- final GEMM: out = x + a @ Wmv^T (K=64) ----
__global__ void __launch_bounds__(256, 2) gemm_final(
    const __half* __restrict__ A, const __half* __restrict__ B,
    const float* __restrict__ Res, float* __restrict__ C)
{
    extern __shared__ char smc[];
    gemm_body<128, true, false>(A, B, Res, C, SEXT, DMODEL,
                                smc, blockIdx.y * 128, blockIdx.x * 128);
}

// =====================================================================
// Fused xa GEMM + ExternalAttention normalization.
// =====================================================================
__global__ void __launch_bounds__(256, 2) gemm_xa_ext(
    const __half* __restrict__ A, const __half* __restrict__ B)
{
    constexpr int BN     = 64;
    constexpr int ABYTES = 128 * 128;
    constexpr int BBYTES = BN * 128;
    constexpr int STB    = ABYTES + BBYTES;
    constexpr int BCH    = 2;
    constexpr int WNT    = 32;
    constexpr int NT     = 4;
    constexpr int MT     = 2;
    constexpr int K      = DMODEL;
    constexpr int TP     = 66;

    extern __shared__ char smc[];
    const uint32_t sbase = smem_u32(smc);

    const int tid  = threadIdx.x;
    const int lane = tid & 31;
    const int wid  = tid >> 5;
    const int wm   = wid & 3;
    const int wn   = wid >> 2;
    const int bm   = blockIdx.y * 128;

    const int mA = tid >> 3;
    const int cA = tid & 7;
    constexpr int nk = K / 64;

    auto issue = [&](int kt, int s) {
        const uint32_t so = (uint32_t)s * STB;
        const int k0 = kt * 64;
#pragma unroll
        for (int i = 0; i < 4; i++) {
            const int m = mA + 32 * i;
            const uint32_t dst = sbase + so + (uint32_t)m * 128u + (uint32_t)((cA ^ (m & 7)) << 4);
            cp16(dst, A + (size_t)(bm + m) * K + k0 + cA * 8);
        }
#pragma unroll
        for (int i = 0; i < BCH; i++) {
            const int m = mA + 32 * i;
            const uint32_t dst = sbase + so + (uint32_t)ABYTES
                               + (uint32_t)m * 128u + (uint32_t)((cA ^ (m & 7)) << 4);
            cp16(dst, B + (size_t)m * K + k0 + cA * 8);
        }
    };

    float acc[MT][NT][4];
#pragma unroll
    for (int i = 0; i < MT; i++)
#pragma unroll
        for (int j = 0; j < NT; j++)
#pragma unroll
            for (int t = 0; t < 4; t++) acc[i][j][t] = 0.f;

    issue(0, 0); CP_COMMIT();
    issue(1, 1); CP_COMMIT();

    uint32_t aaddr[MT];
    {
        const int g = lane >> 3;
        const int arow_in = (g & 1) * 8 + (lane & 7);
        const uint32_t apar = (uint32_t)(g >> 1);
#pragma unroll
        for (int i = 0; i < MT; i++) {
            const int row = wm * 32 + i * 16 + arow_in;
            aaddr[i] = (uint32_t)row * 128u + ((((uint32_t)row & 7u) ^ apar) << 4);
        }
    }
    uint32_t baddr[NT / 2];
    {
        const int g = lane >> 3;
        const int nrow_in = ((g >> 1) & 1) * 8 + (lane & 7);
        const uint32_t bpar = (uint32_t)(g & 1);
#pragma unroll
        for (int jp = 0; jp < NT / 2; jp++) {
            const int n = wn * WNT + jp * 16 + nrow_in;
            baddr[jp] = (uint32_t)n * 128u + ((((uint32_t)n & 7u) ^ bpar) << 4);
        }
    }

    for (int kt = 0; kt < nk; kt++) {
        CP_WAIT1();
        __syncthreads();
        if (kt + 2 < nk) issue(kt + 2, (kt + 2) % 3);
        CP_COMMIT();

        const uint32_t sa = sbase + (uint32_t)(kt % 3) * STB;
        const uint32_t sb = sa + ABYTES;

#pragma unroll
        for (int ks = 0; ks < 4; ks++) {
            const uint32_t kx = (uint32_t)(2 * ks) << 4;
            unsigned af[MT][4], bf[NT][2];
#pragma unroll
            for (int i = 0; i < MT; i++)
                ldsm4(af[i][0], af[i][1], af[i][2], af[i][3], sa + (aaddr[i] ^ kx));
#pragma unroll
            for (int jp = 0; jp < NT / 2; jp++)
                ldsm4(bf[2 * jp][0], bf[2 * jp][1], bf[2 * jp + 1][0], bf[2 * jp + 1][1],
                      sb + (baddr[jp] ^ kx));
#pragma unroll
            for (int i = 0; i < MT; i++)
#pragma unroll
                for (int j = 0; j < NT; j++)
                    mma_f16(acc[i][j], af[i], bf[j]);
        }
    }
    __syncthreads();

    // ---- fused ext-attention epilogue ----
    float* tile = (float*)smc;
    float* rsum = tile + 128 * TP;
#pragma unroll
    for (int i = 0; i < MT; i++) {
#pragma unroll
        for (int j = 0; j < NT; j++) {
            const int rl = wm * 32 + i * 16 + (lane >> 2);
            const int cl = wn * WNT + j * 8 + (lane & 3) * 2;
            *(float2*)&tile[rl * TP + cl]       = make_float2(acc[i][j][0], acc[i][j][1]);
            *(float2*)&tile[(rl + 8) * TP + cl] = make_float2(acc[i][j][2], acc[i][j][3]);
        }
    }
    __syncthreads();

    for (int p = tid; p < 16 * SEXT; p += 256) {
        const int bl = p >> 6, s = p & 63;
        float* col = &tile[(bl * 8) * TP + s];
        float mx = col[0];
#pragma unroll
        for (int m = 1; m < MODAL; m++) mx = fmaxf(mx, col[m * TP]);
        float sum = 0.f;
        float e[MODAL];
#pragma unroll
        for (int m = 0; m < MODAL; m++) { e[m] = expf(col[m * TP] - mx); sum += e[m]; }
        const float is = 1.f / sum;
#pragma unroll
        for (int m = 0; m < MODAL; m++) col[m * TP] = e[m] * is;
    }
    __syncthreads();

    for (int r = tid; r < 128; r += 256) {
        float t = 0.f;
        const float* row = &tile[r * TP];
#pragma unroll
        for (int s = 0; s < SEXT; s++) t += row[s];
        rsum[r] = 1.f / t;
    }
    __syncthreads();

    for (int idx = tid; idx < 128 * (SEXT / 2); idx += 256) {
        const int r = idx >> 5, sp = (idx & 31) * 2;
        const float rs = rsum[r];
        *(__half2*)&g_ah[(size_t)(bm + r) * SEXT + sp] =
            __floats2half2_rn(tile[r * TP + sp] * rs, tile[r * TP + sp + 1] * rs);
    }
}

// =====================================================================
// FUSED attention, fp16 smem operands (register-side fp32 convert).
// softmax(s / ||s||) identity (global-min cancels; see R15).
// smem: qs/ks/vs fp16 [8][QPADH] + sc/aw fp32 [1024] each (~58 KB).
// =====================================================================
constexpr int QPADH = DMODEL + 8;   // halves; row stride 2064 B (16B aligned)
constexpr int ATTN_SMEM = 3 * MODAL * QPADH * 2 + 2048 * 4 + 16;

extern __shared__ char attnsm[];

__global__ void __launch_bounds__(256) attn_fused_kernel() {
    __half* qs = (__half*)attnsm;
    __half* ks = qs + MODAL * QPADH;
    __half* vs = ks + MODAL * QPADH;
    float* sc = (float*)(vs + MODAL * QPADH);   // [16*64]
    float* aw = sc + 1024;                      // [16*64]
    const int b = blockIdx.x, tid = threadIdx.x;

    const uint4* qg = (const uint4*)(g_qph + (size_t)b * MODAL * DMODEL);
    const uint4* kg = (const uint4*)(g_kph + (size_t)b * MODAL * DMODEL);
    const uint4* vg = (const uint4*)(g_vph + (size_t)b * MODAL * DMODEL);
    for (int i = tid; i < MODAL * DMODEL / 8; i += 256) {
        int m = i >> 7, c = i & 127;
        *(uint4*)&qs[m * QPADH + c * 8] = qg[i];
        *(uint4*)&ks[m * QPADH + c * 8] = kg[i];
        *(uint4*)&vs[m * QPADH + c * 8] = vg[i];
    }
    __syncthreads();

    // scores: s[h][m][n] = (q_h[m] . k_h[n]) / 8   (fp32 math)
    for (int s = tid; s < NHEAD * MODAL * MODAL; s += 256) {
        int h = s >> 6, m = (s >> 3) & 7, n = s & 7;
        const uint4* qr = (const uint4*)&qs[m * QPADH + h * DK];
        const uint4* kr = (const uint4*)&ks[n * QPADH + h * DK];
        float acc = 0.f;
#pragma unroll
        for (int d = 0; d < 8; d++) {
            float aq[8], ak[8];
            h8_to_f8(qr[d], aq);
            h8_to_f8(kr[d], ak);
#pragma unroll
            for (int t = 0; t < 8; t++) acc += aq[t] * ak[t];
        }
        sc[s] = acc * 0.125f;
    }
    __syncthreads();

    // per-(h,m) row: softmax(s / ||s||)
    if (tid < 128) {
        int h = tid >> 3, m = tid & 7;
        float r[8]; float ss = 0.f;
#pragma unroll
        for (int n = 0; n < 8; n++) { r[n] = sc[h * 64 + m * 8 + n]; ss += r[n] * r[n]; }
        const float rn = 1.f / fmaxf(sqrtf(ss), 1e-30f);
        float mx = -3.4e38f;
#pragma unroll
        for (int n = 0; n < 8; n++) { r[n] *= rn; mx = fmaxf(mx, r[n]); }
        float sum = 0.f;
#pragma unroll
        for (int n = 0; n < 8; n++) { r[n] = expf(r[n] - mx); sum += r[n]; }
        const float is = 1.f / sum;
#pragma unroll
        for (int n = 0; n < 8; n++) aw[h * 64 + m * 8 + n] = r[n] * is;
    }
    __syncthreads();

    // out = attn @ V -> fp16 (half2 granularity)
    __half2* og = (__half2*)(g_atth + (size_t)b * MODAL * DMODEL);
    for (int o = tid; o < MODAL * DMODEL / 2; o += 256) {
        int m = o >> 9, colp = o & 511, h = colp >> 5;
        float ax = 0.f, ay = 0.f;
        const float* awr = &aw[h * 64 + m * 8];
#pragma unroll
        for (int n = 0; n < 8; n++) {
            float2 vv = __half22float2(*(const __half2*)&vs[n * QPADH + colp * 2]);
            ax += awr[n] * vv.x;
            ay += awr[n] * vv.y;
        }
        og[o] = __floats2half2_rn(ax, ay);
    }
}

// ---------------- LayerNorm: fp32 x in -> fp32 out + fp16 copy ----------------
__global__ void __launch_bounds__(256) ln_kernel(
    const float* __restrict__ gamma, const float* __restrict__ beta,
    float* __restrict__ out)
{
    const int wid = threadIdx.x >> 5, lane = threadIdx.x & 31;
    const size_t row = (size_t)blockIdx.x * 8 + wid;
    const float4* xr = (const float4*)(g_x + row * DMODEL);
    float4 v[8];
    float s = 0.f, s2 = 0.f;
#pragma unroll
    for (int i = 0; i < 8; i++) {
        v[i] = xr[lane + 32 * i];
        s += v[i].x + v[i].y + v[i].z + v[i].w;
        s2 += v[i].x * v[i].x + v[i].y * v[i].y + v[i].z * v[i].z + v[i].w * v[i].w;
    }
#pragma unroll
    for (int o = 16; o; o >>= 1) {
        s += __shfl_xor_sync(0xffffffffu, s, o);
        s2 += __shfl_xor_sync(0xffffffffu, s2, o);
    }
    const float mu = s * (1.f / DMODEL);
    const float var = fmaxf(s2 * (1.f / DMODEL) - mu * mu, 0.f);
    const float rs = rsqrtf(var + 1e-10f);
    float4* orow = (float4*)(out + row * DMODEL);
    __half2* hrow = (__half2*)(g_xh + row * DMODEL);
    const float4* gm = (const float4*)gamma;
    const float4* bt = (const float4*)beta;
#pragma unroll
    for (int i = 0; i < 8; i++) {
        int c4 = lane + 32 * i;
        float4 g = gm[c4], bb = bt[c4], x = v[i], r;
        r.x = (x.x - mu) * rs * g.x + bb.x;
        r.y = (x.y - mu) * rs * g.y + bb.y;
        r.z = (x.z - mu) * rs * g.z + bb.z;
        r.w = (x.w - mu) * rs * g.w + bb.w;
        orow[c4] = r;
        hrow[2 * c4]     = __float22half2_rn(make_float2(r.x, r.y));
        hrow[2 * c4 + 1] = __float22half2_rn(make_float2(r.z, r.w));
    }
}

// ---------------- launch ----------------
extern "C" void kernel_launch(void* const* d_in, const int* in_sizes, int n_in,
                              void* d_out, int out_size)
{
    const float* q     = (const float*)d_in[0];
    const float* k     = (const float*)d_in[1];
    const float* v     = (const float*)d_in[2];
    const float* Wq    = (const float*)d_in[3];
    const float* Wk    = (const float*)d_in[4];
    const float* Wv    = (const float*)d_in[5];
    const float* Wfc   = (const float*)d_in[6];
    const float* gamma = (const float*)d_in[7];
    const float* beta  = (const float*)d_in[8];
    const float* Wmk   = (const float*)d_in[9];
    const float* Wmv   = (const float*)d_in[10];
    float* out = (float*)d_out;

    float *px;
    __half *pqh, *pkh, *pvh, *pqph, *pkph, *pvph, *patth, *pxh, *pah;
    __half *pwqh, *pwkh, *pwvh, *pwfch, *pwmkh, *pwmvh;
    cudaGetSymbolAddress((void**)&px,    g_x);
    cudaGetSymbolAddress((void**)&pqh,   g_qh);
    cudaGetSymbolAddress((void**)&pkh,   g_kh);
    cudaGetSymbolAddress((void**)&pvh,   g_vh);
    cudaGetSymbolAddress((void**)&pqph,  g_qph);
    cudaGetSymbolAddress((void**)&pkph,  g_kph);
    cudaGetSymbolAddress((void**)&pvph,  g_vph);
    cudaGetSymbolAddress((void**)&patth, g_atth);
    cudaGetSymbolAddress((void**)&pxh,   g_xh);
    cudaGetSymbolAddress((void**)&pah,   g_ah);
    cudaGetSymbolAddress((void**)&pwqh,  g_wqh);
    cudaGetSymbolAddress((void**)&pwkh,  g_wkh);
    cudaGetSymbolAddress((void**)&pwvh,  g_wvh);
    cudaGetSymbolAddress((void**)&pwfch, g_wfch);
    cudaGetSymbolAddress((void**)&pwmkh, g_wmkh);
    cudaGetSymbolAddress((void**)&pwmvh, g_wmvh);

    cudaFuncSetAttribute(attn_fused_kernel,
                         cudaFuncAttributeMaxDynamicSharedMemorySize, ATTN_SMEM);

    const int smem128 = 3 * (128 * 128 + 128 * 128);  // 98304 B
    const int smem64  = 3 * (128 * 128 + 64 * 128);   // 73728 B
    cudaFuncSetAttribute(gemm_proj3,
                         cudaFuncAttributeMaxDynamicSharedMemorySize, smem128);
    cudaFuncSetAttribute(gemm_fc,
                         cudaFuncAttributeMaxDynamicSharedMemorySize, smem128);
    cudaFuncSetAttribute(gemm_final,
                         cudaFuncAttributeMaxDynamicSharedMemorySize, smem128);
    cudaFuncSetAttribute(gemm_xa_ext,
                         cudaFuncAttributeMaxDynamicSharedMemorySize, smem64);

    const int a4 = ROWS * DMODEL / 4;
    const int w4 = DMODEL * DMODEL / 4;
    const int s4 = SEXT * DMODEL / 4;

    // fused conversions: activations (3 slots), weights (6 slots)
    cvt_act_kernel<<<dim3((a4 + 255) / 256, 3), 256>>>(
        (const float4*)q, (const float4*)k, (const float4*)v,
        (__half2*)pqh, (__half2*)pkh, (__half2*)pvh, a4);
    cvt_w_kernel<<<dim3((w4 + 255) / 256, 6), 256>>>(
        (const float4*)Wq, (const float4*)Wk, (const float4*)Wv, (const float4*)Wfc,
        (const float4*)Wmk, (const float4*)Wmv,
        (__half2*)pwqh, (__half2*)pwkh, (__half2*)pwvh, (__half2*)pwfch,
        (__half2*)pwmkh, (__half2*)pwmvh, w4, s4);

    // fused q/k/v projections
    gemm_proj3<<<dim3(DMODEL / 128, ROWS / 128, 3), 256, smem128>>>(
        pqh, pkh, pvh, pwqh, pwkh, pwvh, pqph, pkph, pvph);

    // fused attention (fp16 smem operands)
    attn_fused_kernel<<<BSZ, 256, ATTN_SMEM>>>();

    // x = attn_out @ Wfc^T + q (fp32 residual)
    gemm_fc<<<dim3(DMODEL / 128, ROWS / 128), 256, smem128>>>(patth, pwfch, q, px);

    // LayerNorm -> out (fp32) + g_xh (fp16)
    ln_kernel<<<ROWS / 8, 256>>>(gamma, beta, out);

    // fused: xa = x @ Wmk^T + softmax/renorm -> g_ah (fp16)
    gemm_xa_ext<<<dim3(1, ROWS / 128), 256, smem64>>>(pxh, pwmkh);

    // out = x + a @ Wmv^T (K=64)
    gemm_final<<<dim3(DMODEL / 128, ROWS / 128), 256, smem128>>>(pah, pwmvh, out, out);
}

// round 17
// speedup vs baseline: 1.2376x; 1.0297x over previous
#include <cuda_runtime.h>
#include <cuda_fp16.h>
#include <cstdint>

// ---------------- problem constants ----------------
constexpr int MODAL  = 8;
constexpr int DMODEL = 1024;
constexpr int NHEAD  = 16;
constexpr int DK     = 64;
constexpr int SEXT   = 64;
constexpr int BSZ    = 4096;
constexpr int ROWS   = BSZ * MODAL;   // 32768

// ---------------- scratch (device globals) ----------------
__device__ float g_x  [(size_t)ROWS * DMODEL];
// fp16 operands
__device__ __half g_qh  [(size_t)ROWS * DMODEL];
__device__ __half g_kh  [(size_t)ROWS * DMODEL];
__device__ __half g_vh  [(size_t)ROWS * DMODEL];
__device__ __half g_qph [(size_t)ROWS * DMODEL];
__device__ __half g_kph [(size_t)ROWS * DMODEL];
__device__ __half g_vph [(size_t)ROWS * DMODEL];
__device__ __half g_atth[(size_t)ROWS * DMODEL];
__device__ __half g_xh  [(size_t)ROWS * DMODEL];
__device__ __half g_ah  [(size_t)ROWS * SEXT];
__device__ __half g_wqh [(size_t)DMODEL * DMODEL];
__device__ __half g_wkh [(size_t)DMODEL * DMODEL];
__device__ __half g_wvh [(size_t)DMODEL * DMODEL];
__device__ __half g_wfch[(size_t)DMODEL * DMODEL];
__device__ __half g_wmkh[(size_t)SEXT * DMODEL];
__device__ __half g_wmvh[(size_t)DMODEL * SEXT];

// ---------------- helpers ----------------
__device__ __forceinline__ void mma_f16(float* c, const unsigned* a, const unsigned* b) {
    asm volatile(
        "mma.sync.aligned.m16n8k16.row.col.f32.f16.f16.f32 "
        "{%0,%1,%2,%3}, {%4,%5,%6,%7}, {%8,%9}, {%0,%1,%2,%3};\n"
        : "+f"(c[0]), "+f"(c[1]), "+f"(c[2]), "+f"(c[3])
        : "r"(a[0]), "r"(a[1]), "r"(a[2]), "r"(a[3]),
          "r"(b[0]), "r"(b[1]));
}
__device__ __forceinline__ void ldsm4(unsigned& r0, unsigned& r1, unsigned& r2, unsigned& r3,
                                      uint32_t a) {
    asm volatile("ldmatrix.sync.aligned.m8n8.x4.shared.b16 {%0,%1,%2,%3}, [%4];"
                 : "=r"(r0), "=r"(r1), "=r"(r2), "=r"(r3) : "r"(a));
}
__device__ __forceinline__ uint32_t smem_u32(const void* p) {
    uint32_t a;
    asm("{ .reg .u64 t; cvta.to.shared.u64 t, %1; cvt.u32.u64 %0, t; }" : "=r"(a) : "l"(p));
    return a;
}
__device__ __forceinline__ void cp16(uint32_t dst, const void* src) {
    asm volatile("cp.async.cg.shared.global [%0], [%1], 16;" :: "r"(dst), "l"(src));
}
#define CP_COMMIT() asm volatile("cp.async.commit_group;" ::: "memory")
#define CP_WAIT1()  asm volatile("cp.async.wait_group 1;" ::: "memory")

// unpack 8 halves (one uint4) -> 8 floats at dst
__device__ __forceinline__ void h8_to_f8(uint4 u, float* dst) {
    const __half2* hp = (const __half2*)&u;
    float2 f0 = __half22float2(hp[0]);
    float2 f1 = __half22float2(hp[1]);
    float2 f2 = __half22float2(hp[2]);
    float2 f3 = __half22float2(hp[3]);
    dst[0] = f0.x; dst[1] = f0.y; dst[2] = f1.x; dst[3] = f1.y;
    dst[4] = f2.x; dst[5] = f2.y; dst[6] = f3.x; dst[7] = f3.y;
}

// ---------------- fused fp32->fp16 conversions ----------------
__global__ void __launch_bounds__(256) cvt_act_kernel(
    const float4* __restrict__ s0, const float4* __restrict__ s1, const float4* __restrict__ s2,
    __half2* __restrict__ d0, __half2* __restrict__ d1, __half2* __restrict__ d2, int n4)
{
    const int z = blockIdx.y;
    const float4* s = (z == 0) ? s0 : (z == 1) ? s1 : s2;
    __half2* d = (z == 0) ? d0 : (z == 1) ? d1 : d2;
    int i = blockIdx.x * 256 + threadIdx.x;
    if (i < n4) {
        float4 v = s[i];
        d[2 * i]     = __float22half2_rn(make_float2(v.x, v.y));
        d[2 * i + 1] = __float22half2_rn(make_float2(v.z, v.w));
    }
}

__global__ void __launch_bounds__(256) cvt_w_kernel(
    const float4* __restrict__ s0, const float4* __restrict__ s1,
    const float4* __restrict__ s2, const float4* __restrict__ s3,
    const float4* __restrict__ s4, const float4* __restrict__ s5,
    __half2* __restrict__ d0, __half2* __restrict__ d1,
    __half2* __restrict__ d2, __half2* __restrict__ d3,
    __half2* __restrict__ d4, __half2* __restrict__ d5,
    int nbig, int nsmall)
{
    const int z = blockIdx.y;
    const float4* sa[6] = { s0, s1, s2, s3, s4, s5 };
    __half2* da[6] = { d0, d1, d2, d3, d4, d5 };
    const int n4 = (z < 4) ? nbig : nsmall;
    int i = blockIdx.x * 256 + threadIdx.x;
    if (i < n4) {
        float4 v = sa[z][i];
        da[z][2 * i]     = __float22half2_rn(make_float2(v.x, v.y));
        da[z][2 * i + 1] = __float22half2_rn(make_float2(v.z, v.w));
    }
}

// =====================================================================
// Shared GEMM body: C[M,N] = A[M,K] * B[N,K]^T (+ Res fp32).
// BM=128, BK=64, BN in {128,64}. 256 thr, 8 warps (4Mx2N).
// 3-stage cp.async pipeline, one __syncthreads per k-tile.
// =====================================================================
template<int BN, bool RES, bool OUTH>
__device__ __forceinline__ void gemm_body(
    const __half* __restrict__ A, const __half* __restrict__ B,
    const float* __restrict__ Res, void* __restrict__ Cv, int K, int N,
    char* smc, int bm, int bn)
{
    constexpr int ABYTES = 128 * 128;
    constexpr int BBYTES = BN * 128;
    constexpr int STB    = ABYTES + BBYTES;
    constexpr int BCH    = BN * 8 / 256;
    constexpr int WNT    = BN / 2;
    constexpr int NT     = WNT / 8;
    constexpr int MT     = 2;

    const uint32_t sbase = smem_u32(smc);
    const int tid  = threadIdx.x;
    const int lane = tid & 31;
    const int wid  = tid >> 5;
    const int wm   = wid & 3;
    const int wn   = wid >> 2;

    const int mA = tid >> 3;
    const int cA = tid & 7;
    const int nk = K / 64;

    auto issue = [&](int kt, int s) {
        const uint32_t so = (uint32_t)s * STB;
        const int k0 = kt * 64;
#pragma unroll
        for (int i = 0; i < 4; i++) {
            const int m = mA + 32 * i;
            const uint32_t dst = sbase + so + (uint32_t)m * 128u + (uint32_t)((cA ^ (m & 7)) << 4);
            cp16(dst, A + (size_t)(bm + m) * K + k0 + cA * 8);
        }
#pragma unroll
        for (int i = 0; i < BCH; i++) {
            const int m = mA + 32 * i;
            const uint32_t dst = sbase + so + (uint32_t)ABYTES
                               + (uint32_t)m * 128u + (uint32_t)((cA ^ (m & 7)) << 4);
            cp16(dst, B + (size_t)(bn + m) * K + k0 + cA * 8);
        }
    };

    float acc[MT][NT][4];
#pragma unroll
    for (int i = 0; i < MT; i++)
#pragma unroll
        for (int j = 0; j < NT; j++)
#pragma unroll
            for (int t = 0; t < 4; t++) acc[i][j][t] = 0.f;

    issue(0, 0); CP_COMMIT();
    if (nk > 1) issue(1, 1);
    CP_COMMIT();

    uint32_t aaddr[MT];
    {
        const int g = lane >> 3;
        const int arow_in = (g & 1) * 8 + (lane & 7);
        const uint32_t apar = (uint32_t)(g >> 1);
#pragma unroll
        for (int i = 0; i < MT; i++) {
            const int row = wm * 32 + i * 16 + arow_in;
            aaddr[i] = (uint32_t)row * 128u + ((((uint32_t)row & 7u) ^ apar) << 4);
        }
    }
    uint32_t baddr[NT / 2];
    {
        const int g = lane >> 3;
        const int nrow_in = ((g >> 1) & 1) * 8 + (lane & 7);
        const uint32_t bpar = (uint32_t)(g & 1);
#pragma unroll
        for (int jp = 0; jp < NT / 2; jp++) {
            const int n = wn * WNT + jp * 16 + nrow_in;
            baddr[jp] = (uint32_t)n * 128u + ((((uint32_t)n & 7u) ^ bpar) << 4);
        }
    }

    for (int kt = 0; kt < nk; kt++) {
        CP_WAIT1();
        __syncthreads();
        if (kt + 2 < nk) issue(kt + 2, (kt + 2) % 3);
        CP_COMMIT();

        const uint32_t sa = sbase + (uint32_t)(kt % 3) * STB;
        const uint32_t sb = sa + ABYTES;

#pragma unroll
        for (int ks = 0; ks < 4; ks++) {
            const uint32_t kx = (uint32_t)(2 * ks) << 4;
            unsigned af[MT][4], bf[NT][2];
#pragma unroll
            for (int i = 0; i < MT; i++)
                ldsm4(af[i][0], af[i][1], af[i][2], af[i][3], sa + (aaddr[i] ^ kx));
#pragma unroll
            for (int jp = 0; jp < NT / 2; jp++)
                ldsm4(bf[2 * jp][0], bf[2 * jp][1], bf[2 * jp + 1][0], bf[2 * jp + 1][1],
                      sb + (baddr[jp] ^ kx));
#pragma unroll
            for (int i = 0; i < MT; i++)
#pragma unroll
                for (int j = 0; j < NT; j++)
                    mma_f16(acc[i][j], af[i], bf[j]);
        }
    }

#pragma unroll
    for (int i = 0; i < MT; i++) {
#pragma unroll
        for (int j = 0; j < NT; j++) {
            const int r0 = bm + wm * 32 + i * 16 + (lane >> 2);
            const int c0 = bn + wn * WNT + j * 8 + (lane & 3) * 2;
            float2 v0 = make_float2(acc[i][j][0], acc[i][j][1]);
            float2 v1 = make_float2(acc[i][j][2], acc[i][j][3]);
            if (OUTH) {
                __half* Co = (__half*)Cv;
                *(__half2*)&Co[(size_t)r0 * N + c0]       = __floats2half2_rn(v0.x, v0.y);
                *(__half2*)&Co[(size_t)(r0 + 8) * N + c0] = __floats2half2_rn(v1.x, v1.y);
            } else {
                float* Cf = (float*)Cv;
                if (RES) {
                    float2 ra = *(const float2*)&Res[(size_t)r0 * N + c0];
                    float2 rb = *(const float2*)&Res[(size_t)(r0 + 8) * N + c0];
                    v0.x += ra.x; v0.y += ra.y;
                    v1.x += rb.x; v1.y += rb.y;
                }
                *(float2*)&Cf[(size_t)r0 * N + c0] = v0;
                *(float2*)&Cf[(size_t)(r0 + 8) * N + c0] = v1;
            }
        }
    }
}

// ---- fused 3-way projection GEMM (grid.z selects q/k/v) ----
__global__ void __launch_bounds__(256, 2) gemm_proj3(
    const __half* A0, const __half* A1, const __half* A2,
    const __half* B0, const __half* B1, const __half* B2,
    __half* C0, __half* C1, __half* C2)
{
    extern __shared__ char smc[];
    const int z = blockIdx.z;
    const __half* A = (z == 0) ? A0 : (z == 1) ? A1 : A2;
    const __half* B = (z == 0) ? B0 : (z == 1) ? B1 : B2;
    __half* C = (z == 0) ? C0 : (z == 1) ? C1 : C2;
    gemm_body<128, false, true>(A, B, nullptr, C, DMODEL, DMODEL,
                                smc, blockIdx.y * 128, blockIdx.x * 128);
}

// ---- FC GEMM: x = attn_out @ Wfc^T + q (fp32 out) ----
__global__ void __launch_bounds__(256, 2) gemm_fc(
    const __half* __restrict__ A, const __half* __restrict__ B,
    const float* __restrict__ Res, float* __restrict__ C)
{
    extern __shared__ char smc[];
    gemm_body<128, true, false>(A, B, Res, C, DMODEL, DMODEL,
                                smc, blockIdx.y * 128, blockIdx.x * 128);
}

// ---- final GEMM: out = x + a @ Wmv^T (K=64) ----
__global__ void __launch_bounds__(256, 2) gemm_final(
    const __half* __restrict__ A, const __half* __restrict__ B,
    const float* __restrict__ Res, float* __restrict__ C)
{
    extern __shared__ char smc[];
    gemm_body<128, true, false>(A, B, Res, C, SEXT, DMODEL,
                                smc, blockIdx.y * 128, blockIdx.x * 128);
}

// =====================================================================
// Fused xa GEMM + ExternalAttention normalization.
// =====================================================================
__global__ void __launch_bounds__(256, 2) gemm_xa_ext(
    const __half* __restrict__ A, const __half* __restrict__ B)
{
    constexpr int BN     = 64;
    constexpr int ABYTES = 128 * 128;
    constexpr int BBYTES = BN * 128;
    constexpr int STB    = ABYTES + BBYTES;
    constexpr int BCH    = 2;
    constexpr int WNT    = 32;
    constexpr int NT     = 4;
    constexpr int MT     = 2;
    constexpr int K      = DMODEL;
    constexpr int TP     = 66;

    extern __shared__ char smc[];
    const uint32_t sbase = smem_u32(smc);

    const int tid  = threadIdx.x;
    const int lane = tid & 31;
    const int wid  = tid >> 5;
    const int wm   = wid & 3;
    const int wn   = wid >> 2;
    const int bm   = blockIdx.y * 128;

    const int mA = tid >> 3;
    const int cA = tid & 7;
    constexpr int nk = K / 64;

    auto issue = [&](int kt, int s) {
        const uint32_t so = (uint32_t)s * STB;
        const int k0 = kt * 64;
#pragma unroll
        for (int i = 0; i < 4; i++) {
            const int m = mA + 32 * i;
            const uint32_t dst = sbase + so + (uint32_t)m * 128u + (uint32_t)((cA ^ (m & 7)) << 4);
            cp16(dst, A + (size_t)(bm + m) * K + k0 + cA * 8);
        }
#pragma unroll
        for (int i = 0; i < BCH; i++) {
            const int m = mA + 32 * i;
            const uint32_t dst = sbase + so + (uint32_t)ABYTES
                               + (uint32_t)m * 128u + (uint32_t)((cA ^ (m & 7)) << 4);
            cp16(dst, B + (size_t)m * K + k0 + cA * 8);
        }
    };

    float acc[MT][NT][4];
#pragma unroll
    for (int i = 0; i < MT; i++)
#pragma unroll
        for (int j = 0; j < NT; j++)
#pragma unroll
            for (int t = 0; t < 4; t++) acc[i][j][t] = 0.f;

    issue(0, 0); CP_COMMIT();
    issue(1, 1); CP_COMMIT();

    uint32_t aaddr[MT];
    {
        const int g = lane >> 3;
        const int arow_in = (g & 1) * 8 + (lane & 7);
        const uint32_t apar = (uint32_t)(g >> 1);
#pragma unroll
        for (int i = 0; i < MT; i++) {
            const int row = wm * 32 + i * 16 + arow_in;
            aaddr[i] = (uint32_t)row * 128u + ((((uint32_t)row & 7u) ^ apar) << 4);
        }
    }
    uint32_t baddr[NT / 2];
    {
        const int g = lane >> 3;
        const int nrow_in = ((g >> 1) & 1) * 8 + (lane & 7);
        const uint32_t bpar = (uint32_t)(g & 1);
#pragma unroll
        for (int jp = 0; jp < NT / 2; jp++) {
            const int n = wn * WNT + jp * 16 + nrow_in;
            baddr[jp] = (uint32_t)n * 128u + ((((uint32_t)n & 7u) ^ bpar) << 4);
        }
    }

    for (int kt = 0; kt < nk; kt++) {
        CP_WAIT1();
        __syncthreads();
        if (kt + 2 < nk) issue(kt + 2, (kt + 2) % 3);
        CP_COMMIT();

        const uint32_t sa = sbase + (uint32_t)(kt % 3) * STB;
        const uint32_t sb = sa + ABYTES;

#pragma unroll
        for (int ks = 0; ks < 4; ks++) {
            const uint32_t kx = (uint32_t)(2 * ks) << 4;
            unsigned af[MT][4], bf[NT][2];
#pragma unroll
            for (int i = 0; i < MT; i++)
                ldsm4(af[i][0], af[i][1], af[i][2], af[i][3], sa + (aaddr[i] ^ kx));
#pragma unroll
            for (int jp = 0; jp < NT / 2; jp++)
                ldsm4(bf[2 * jp][0], bf[2 * jp][1], bf[2 * jp + 1][0], bf[2 * jp + 1][1],
                      sb + (baddr[jp] ^ kx));
#pragma unroll
            for (int i = 0; i < MT; i++)
#pragma unroll
                for (int j = 0; j < NT; j++)
                    mma_f16(acc[i][j], af[i], bf[j]);
        }
    }
    __syncthreads();

    // ---- fused ext-attention epilogue ----
    float* tile = (float*)smc;
    float* rsum = tile + 128 * TP;
#pragma unroll
    for (int i = 0; i < MT; i++) {
#pragma unroll
        for (int j = 0; j < NT; j++) {
            const int rl = wm * 32 + i * 16 + (lane >> 2);
            const int cl = wn * WNT + j * 8 + (lane & 3) * 2;
            *(float2*)&tile[rl * TP + cl]       = make_float2(acc[i][j][0], acc[i][j][1]);
            *(float2*)&tile[(rl + 8) * TP + cl] = make_float2(acc[i][j][2], acc[i][j][3]);
        }
    }
    __syncthreads();

    for (int p = tid; p < 16 * SEXT; p += 256) {
        const int bl = p >> 6, s = p & 63;
        float* col = &tile[(bl * 8) * TP + s];
        float mx = col[0];
#pragma unroll
        for (int m = 1; m < MODAL; m++) mx = fmaxf(mx, col[m * TP]);
        float sum = 0.f;
        float e[MODAL];
#pragma unroll
        for (int m = 0; m < MODAL; m++) { e[m] = expf(col[m * TP] - mx); sum += e[m]; }
        const float is = 1.f / sum;
#pragma unroll
        for (int m = 0; m < MODAL; m++) col[m * TP] = e[m] * is;
    }
    __syncthreads();

    for (int r = tid; r < 128; r += 256) {
        float t = 0.f;
        const float* row = &tile[r * TP];
#pragma unroll
        for (int s = 0; s < SEXT; s++) t += row[s];
        rsum[r] = 1.f / t;
    }
    __syncthreads();

    for (int idx = tid; idx < 128 * (SEXT / 2); idx += 256) {
        const int r = idx >> 5, sp = (idx & 31) * 2;
        const float rs = rsum[r];
        *(__half2*)&g_ah[(size_t)(bm + r) * SEXT + sp] =
            __floats2half2_rn(tile[r * TP + sp] * rs, tile[r * TP + sp + 1] * rs);
    }
}

// =====================================================================
// FUSED attention, fp16 smem, reduced-LDS mapping.
// softmax(s / ||s||) identity (global-min cancels; see R15).
// Score phase: thread pair owns one (h,m); q-row registered once.
// attn@V: uint4 outputs (8 V LDS.128 + 8 broadcast aw per output).
// =====================================================================
constexpr int QPADH = DMODEL + 8;   // halves; row stride 2064 B
constexpr int ATTN_SMEM = 3 * MODAL * QPADH * 2 + 2048 * 4 + 16;

extern __shared__ char attnsm[];

__global__ void __launch_bounds__(256) attn_fused_kernel() {
    __half* qs = (__half*)attnsm;
    __half* ks = qs + MODAL * QPADH;
    __half* vs = ks + MODAL * QPADH;
    float* sc = (float*)(vs + MODAL * QPADH);   // [16*64]
    float* aw = sc + 1024;                      // [16*64]
    const int b = blockIdx.x, tid = threadIdx.x;

    const uint4* qg = (const uint4*)(g_qph + (size_t)b * MODAL * DMODEL);
    const uint4* kg = (const uint4*)(g_kph + (size_t)b * MODAL * DMODEL);
    const uint4* vg = (const uint4*)(g_vph + (size_t)b * MODAL * DMODEL);
    for (int i = tid; i < MODAL * DMODEL / 8; i += 256) {
        int m = i >> 7, c = i & 127;
        *(uint4*)&qs[m * QPADH + c * 8] = qg[i];
        *(uint4*)&ks[m * QPADH + c * 8] = kg[i];
        *(uint4*)&vs[m * QPADH + c * 8] = vg[i];
    }
    __syncthreads();

    // scores: thread pair (tid, tid^1) shares (h,m); each covers 4 n's.
    {
        const int hm = tid >> 1;               // 0..127
        const int h = hm >> 3, m = hm & 7;
        const int n0 = (tid & 1) * 4;
        const uint4* qr = (const uint4*)&qs[m * QPADH + h * DK];
        uint4 qreg[8];
#pragma unroll
        for (int d = 0; d < 8; d++) qreg[d] = qr[d];
#pragma unroll
        for (int nn = 0; nn < 4; nn++) {
            const int n = n0 + nn;
            const uint4* kr = (const uint4*)&ks[n * QPADH + h * DK];
            float acc = 0.f;
#pragma unroll
            for (int d = 0; d < 8; d++) {
                float fq[8], fk[8];
                h8_to_f8(qreg[d], fq);
                h8_to_f8(kr[d], fk);
#pragma unroll
                for (int t = 0; t < 8; t++) acc += fq[t] * fk[t];
            }
            sc[h * 64 + m * 8 + n] = acc * 0.125f;
        }
    }
    __syncthreads();

    // per-(h,m) row: softmax(s / ||s||)
    if (tid < 128) {
        int h = tid >> 3, m = tid & 7;
        float r[8]; float ss = 0.f;
#pragma unroll
        for (int n = 0; n < 8; n++) { r[n] = sc[h * 64 + m * 8 + n]; ss += r[n] * r[n]; }
        const float rn = 1.f / fmaxf(sqrtf(ss), 1e-30f);
        float mx = -3.4e38f;
#pragma unroll
        for (int n = 0; n < 8; n++) { r[n] *= rn; mx = fmaxf(mx, r[n]); }
        float sum = 0.f;
#pragma unroll
        for (int n = 0; n < 8; n++) { r[n] = expf(r[n] - mx); sum += r[n]; }
        const float is = 1.f / sum;
#pragma unroll
        for (int n = 0; n < 8; n++) aw[h * 64 + m * 8 + n] = r[n] * is;
    }
    __syncthreads();

    // out = attn @ V -> fp16, one uint4 (8 halves) per step
    uint4* og = (uint4*)(g_atth + (size_t)b * MODAL * DMODEL);
#pragma unroll
    for (int i = 0; i < 4; i++) {
        const int o = tid + 256 * i;           // 0..1023 uint4 outputs
        const int m = o >> 7, c8 = o & 127, h = c8 >> 3;
        const float* awr = &aw[h * 64 + m * 8];
        float acc8[8];
#pragma unroll
        for (int t = 0; t < 8; t++) acc8[t] = 0.f;
#pragma unroll
        for (int n = 0; n < 8; n++) {
            const float w = awr[n];
            float fv[8];
            h8_to_f8(*(const uint4*)&vs[n * QPADH + c8 * 8], fv);
#pragma unroll
            for (int t = 0; t < 8; t++) acc8[t] += w * fv[t];
        }
        uint4 pack;
        __half2* hp = (__half2*)&pack;
        hp[0] = __floats2half2_rn(acc8[0], acc8[1]);
        hp[1] = __floats2half2_rn(acc8[2], acc8[3]);
        hp[2] = __floats2half2_rn(acc8[4], acc8[5]);
        hp[3] = __floats2half2_rn(acc8[6], acc8[7]);
        og[o] = pack;
    }
}

// ---------------- LayerNorm: fp32 x in -> fp32 out + fp16 copy ----------------
__global__ void __launch_bounds__(256) ln_kernel(
    const float* __restrict__ gamma, const float* __restrict__ beta,
    float* __restrict__ out)
{
    const int wid = threadIdx.x >> 5, lane = threadIdx.x & 31;
    const size_t row = (size_t)blockIdx.x * 8 + wid;
    const float4* xr = (const float4*)(g_x + row * DMODEL);
    float4 v[8];
    float s = 0.f, s2 = 0.f;
#pragma unroll
    for (int i = 0; i < 8; i++) {
        v[i] = xr[lane + 32 * i];
        s += v[i].x + v[i].y + v[i].z + v[i].w;
        s2 += v[i].x * v[i].x + v[i].y * v[i].y + v[i].z * v[i].z + v[i].w * v[i].w;
    }
#pragma unroll
    for (int o = 16; o; o >>= 1) {
        s += __shfl_xor_sync(0xffffffffu, s, o);
        s2 += __shfl_xor_sync(0xffffffffu, s2, o);
    }
    const float mu = s * (1.f / DMODEL);
    const float var = fmaxf(s2 * (1.f / DMODEL) - mu * mu, 0.f);
    const float rs = rsqrtf(var + 1e-10f);
    float4* orow = (float4*)(out + row * DMODEL);
    __half2* hrow = (__half2*)(g_xh + row * DMODEL);
    const float4* gm = (const float4*)gamma;
    const float4* bt = (const float4*)beta;
#pragma unroll
    for (int i = 0; i < 8; i++) {
        int c4 = lane + 32 * i;
        float4 g = gm[c4], bb = bt[c4], x = v[i], r;
        r.x = (x.x - mu) * rs * g.x + bb.x;
        r.y = (x.y - mu) * rs * g.y + bb.y;
        r.z = (x.z - mu) * rs * g.z + bb.z;
        r.w = (x.w - mu) * rs * g.w + bb.w;
        orow[c4] = r;
        hrow[2 * c4]     = __float22half2_rn(make_float2(r.x, r.y));
        hrow[2 * c4 + 1] = __float22half2_rn(make_float2(r.z, r.w));
    }
}

// ---------------- launch ----------------
extern "C" void kernel_launch(void* const* d_in, const int* in_sizes, int n_in,
                              void* d_out, int out_size)
{
    const float* q     = (const float*)d_in[0];
    const float* k     = (const float*)d_in[1];
    const float* v     = (const float*)d_in[2];
    const float* Wq    = (const float*)d_in[3];
    const float* Wk    = (const float*)d_in[4];
    const float* Wv    = (const float*)d_in[5];
    const float* Wfc   = (const float*)d_in[6];
    const float* gamma = (const float*)d_in[7];
    const float* beta  = (const float*)d_in[8];
    const float* Wmk   = (const float*)d_in[9];
    const float* Wmv   = (const float*)d_in[10];
    float* out = (float*)d_out;

    float *px;
    __half *pqh, *pkh, *pvh, *pqph, *pkph, *pvph, *patth, *pxh, *pah;
    __half *pwqh, *pwkh, *pwvh, *pwfch, *pwmkh, *pwmvh;
    cudaGetSymbolAddress((void**)&px,    g_x);
    cudaGetSymbolAddress((void**)&pqh,   g_qh);
    cudaGetSymbolAddress((void**)&pkh,   g_kh);
    cudaGetSymbolAddress((void**)&pvh,   g_vh);
    cudaGetSymbolAddress((void**)&pqph,  g_qph);
    cudaGetSymbolAddress((void**)&pkph,  g_kph);
    cudaGetSymbolAddress((void**)&pvph,  g_vph);
    cudaGetSymbolAddress((void**)&patth, g_atth);
    cudaGetSymbolAddress((void**)&pxh,   g_xh);
    cudaGetSymbolAddress((void**)&pah,   g_ah);
    cudaGetSymbolAddress((void**)&pwqh,  g_wqh);
    cudaGetSymbolAddress((void**)&pwkh,  g_wkh);
    cudaGetSymbolAddress((void**)&pwvh,  g_wvh);
    cudaGetSymbolAddress((void**)&pwfch, g_wfch);
    cudaGetSymbolAddress((void**)&pwmkh, g_wmkh);
    cudaGetSymbolAddress((void**)&pwmvh, g_wmvh);

    cudaFuncSetAttribute(attn_fused_kernel,
                         cudaFuncAttributeMaxDynamicSharedMemorySize, ATTN_SMEM);

    const int smem128 = 3 * (128 * 128 + 128 * 128);  // 98304 B
    const int smem64  = 3 * (128 * 128 + 64 * 128);   // 73728 B
    cudaFuncSetAttribute(gemm_proj3,
                         cudaFuncAttributeMaxDynamicSharedMemorySize, smem128);
    cudaFuncSetAttribute(gemm_fc,
                         cudaFuncAttributeMaxDynamicSharedMemorySize, smem128);
    cudaFuncSetAttribute(gemm_final,
                         cudaFuncAttributeMaxDynamicSharedMemorySize, smem128);
    cudaFuncSetAttribute(gemm_xa_ext,
                         cudaFuncAttributeMaxDynamicSharedMemorySize, smem64);

    const int a4 = ROWS * DMODEL / 4;
    const int w4 = DMODEL * DMODEL / 4;
    const int s4 = SEXT * DMODEL / 4;

    // fused conversions: activations (3 slots), weights (6 slots)
    cvt_act_kernel<<<dim3((a4 + 255) / 256, 3), 256>>>(
        (const float4*)q, (const float4*)k, (const float4*)v,
        (__half2*)pqh, (__half2*)pkh, (__half2*)pvh, a4);
    cvt_w_kernel<<<dim3((w4 + 255) / 256, 6), 256>>>(
        (const float4*)Wq, (const float4*)Wk, (const float4*)Wv, (const float4*)Wfc,
        (const float4*)Wmk, (const float4*)Wmv,
        (__half2*)pwqh, (__half2*)pwkh, (__half2*)pwvh, (__half2*)pwfch,
        (__half2*)pwmkh, (__half2*)pwmvh, w4, s4);

    // fused q/k/v projections
    gemm_proj3<<<dim3(DMODEL / 128, ROWS / 128, 3), 256, smem128>>>(
        pqh, pkh, pvh, pwqh, pwkh, pwvh, pqph, pkph, pvph);

    // fused attention
    attn_fused_kernel<<<BSZ, 256, ATTN_SMEM>>>();

    // x = attn_out @ Wfc^T + q (fp32 residual)
    gemm_fc<<<dim3(DMODEL / 128, ROWS / 128), 256, smem128>>>(patth, pwfch, q, px);

    // LayerNorm -> out (fp32) + g_xh (fp16)
    ln_kernel<<<ROWS / 8, 256>>>(gamma, beta, out);

    // fused: xa = x @ Wmk^T + softmax/renorm -> g_ah (fp16)
    gemm_xa_ext<<<dim3(1, ROWS / 128), 256, smem64>>>(pxh, pwmkh);

    // out = x + a @ Wmv^T (K=64)
    gemm_final<<<dim3(DMODEL / 128, ROWS / 128), 256, smem128>>>(pah, pwmvh, out, out);
}